// round 1
// baseline (speedup 1.0000x reference)
#include <cuda_runtime.h>

// Fused masked SDPA, fp32 baseline (flash-style single pass, no running max).
// Grid: (Q/64, B). Block: 128 threads. Smem: 76 KB dynamic -> 2 CTAs/SM.

#define BQ   64
#define BK   32
#define DD   128
#define NTH  128
#define QSTR 132   // Qs row stride in floats (pad to break bank alignment)
#define KSTR 132
#define PSTR 68

__global__ __launch_bounds__(NTH, 2)
void attn_kernel(const float* __restrict__ Qg, const float* __restrict__ Kg,
                 const float* __restrict__ Vg, const int* __restrict__ vlen,
                 float* __restrict__ Og, int Qn, int Kn)
{
    extern __shared__ float smem[];
    float* Qs = smem;                 // [BQ][QSTR]
    float* Ks = Qs + BQ * QSTR;       // [BK][KSTR]
    float* Vs = Ks + BK * KSTR;       // [BK][DD]
    float* Ps = Vs + BK * DD;         // [BK][PSTR]  (P transposed: [j][i])
    float* Ls = Ps + BK * PSTR;       // [BQ] row sums

    const int b     = blockIdx.y;
    const int q0    = blockIdx.x * BQ;
    const int tid   = threadIdx.x;
    const int valid = vlen[b];

    const float scale = 0.088388347648318447f;  // 1/sqrt(128)

    // ---- load Q tile (scale folded in), row-major, coalesced ----
    {
        const float4* Qg4 = (const float4*)(Qg + ((size_t)b * Qn + q0) * DD);
        for (int t = tid; t < BQ * (DD / 4); t += NTH) {
            int i = t >> 5;        // row within tile
            int c = t & 31;        // float4 chunk along d
            float4 v;
            if (q0 + i < Qn) v = Qg4[(size_t)i * (DD / 4) + c];
            else             v = make_float4(0.f, 0.f, 0.f, 0.f);
            float4* dst = (float4*)&Qs[i * QSTR + c * 4];
            float4 w; w.x = v.x * scale; w.y = v.y * scale;
                      w.z = v.z * scale; w.w = v.w * scale;
            *dst = w;
        }
    }

    // Thread tiling:
    //   S-GEMM:  rows {r, r+16, r+32, r+48}, cols c0..c0+3   (64x32 / 128 thr)
    //   O-GEMM:  same rows, cols oc0..oc0+15                 (64x128 / 128 thr)
    const int r   = tid & 15;
    const int cg  = tid >> 4;      // 0..7
    const int c0  = cg * 4;
    const int oc0 = cg * 16;

    float o[4][16];
    #pragma unroll
    for (int ii = 0; ii < 4; ii++)
        #pragma unroll
        for (int cc = 0; cc < 16; cc++) o[ii][cc] = 0.f;
    float lacc[4] = {0.f, 0.f, 0.f, 0.f};

    const int ktiles = (valid + BK - 1) / BK;  // skip fully-masked tiles

    for (int kt = 0; kt < ktiles; kt++) {
        const int k0 = kt * BK;
        __syncthreads();  // previous Ks/Vs/Ps consumers done before overwrite

        // ---- load K and V tiles, row-major, coalesced ----
        {
            const float4* Kg4 = (const float4*)(Kg + ((size_t)b * Kn + k0) * DD);
            const float4* Vg4 = (const float4*)(Vg + ((size_t)b * Kn + k0) * DD);
            for (int t = tid; t < BK * (DD / 4); t += NTH) {
                int j = t >> 5;
                int c = t & 31;
                float4 kv, vv;
                if (k0 + j < Kn) {
                    kv = Kg4[(size_t)j * (DD / 4) + c];
                    vv = Vg4[(size_t)j * (DD / 4) + c];
                } else {
                    kv = make_float4(0.f, 0.f, 0.f, 0.f);
                    vv = kv;
                }
                *(float4*)&Ks[j * KSTR + c * 4] = kv;
                *(float4*)&Vs[j * DD   + c * 4] = vv;
            }
        }
        __syncthreads();

        // ---- S = Q K^T (scale pre-folded into Q) ----
        float s[4][4];
        #pragma unroll
        for (int ii = 0; ii < 4; ii++)
            #pragma unroll
            for (int jj = 0; jj < 4; jj++) s[ii][jj] = 0.f;

        #pragma unroll 8
        for (int d4 = 0; d4 < DD; d4 += 4) {
            float4 qf[4], kf[4];
            qf[0] = *(const float4*)&Qs[(r     ) * QSTR + d4];
            qf[1] = *(const float4*)&Qs[(r + 16) * QSTR + d4];
            qf[2] = *(const float4*)&Qs[(r + 32) * QSTR + d4];
            qf[3] = *(const float4*)&Qs[(r + 48) * QSTR + d4];
            kf[0] = *(const float4*)&Ks[(c0 + 0) * KSTR + d4];
            kf[1] = *(const float4*)&Ks[(c0 + 1) * KSTR + d4];
            kf[2] = *(const float4*)&Ks[(c0 + 2) * KSTR + d4];
            kf[3] = *(const float4*)&Ks[(c0 + 3) * KSTR + d4];
            #pragma unroll
            for (int ii = 0; ii < 4; ii++)
                #pragma unroll
                for (int jj = 0; jj < 4; jj++)
                    s[ii][jj] += qf[ii].x * kf[jj].x + qf[ii].y * kf[jj].y
                               + qf[ii].z * kf[jj].z + qf[ii].w * kf[jj].w;
        }

        // ---- P = exp(S) with key mask; store transposed [j][i] ----
        #pragma unroll
        for (int jj = 0; jj < 4; jj++) {
            const bool ok = (k0 + c0 + jj) < valid;
            #pragma unroll
            for (int ii = 0; ii < 4; ii++) {
                float p = ok ? __expf(s[ii][jj]) : 0.f;
                Ps[(c0 + jj) * PSTR + r + 16 * ii] = p;
            }
        }
        __syncthreads();

        // ---- O += P V ; l += row-sum(P) (free: reuses the P fragment) ----
        #pragma unroll 4
        for (int j = 0; j < BK; j++) {
            float pr[4];
            pr[0] = Ps[j * PSTR + r];
            pr[1] = Ps[j * PSTR + r + 16];
            pr[2] = Ps[j * PSTR + r + 32];
            pr[3] = Ps[j * PSTR + r + 48];
            lacc[0] += pr[0]; lacc[1] += pr[1];
            lacc[2] += pr[2]; lacc[3] += pr[3];
            const float4* vrow = (const float4*)&Vs[j * DD + oc0];
            #pragma unroll
            for (int q4 = 0; q4 < 4; q4++) {
                float4 vv = vrow[q4];
                const int cb = q4 * 4;
                #pragma unroll
                for (int ii = 0; ii < 4; ii++) {
                    o[ii][cb + 0] += pr[ii] * vv.x;
                    o[ii][cb + 1] += pr[ii] * vv.y;
                    o[ii][cb + 2] += pr[ii] * vv.z;
                    o[ii][cb + 3] += pr[ii] * vv.w;
                }
            }
        }
    }

    // ---- epilogue: share row sums, normalize, store ----
    if (cg == 0) {
        #pragma unroll
        for (int ii = 0; ii < 4; ii++) Ls[r + 16 * ii] = lacc[ii];
    }
    __syncthreads();

    #pragma unroll
    for (int ii = 0; ii < 4; ii++) {
        const int qi = q0 + r + 16 * ii;
        if (qi >= Qn) continue;
        const float inv = 1.0f / Ls[r + 16 * ii];
        float4* dst = (float4*)(Og + ((size_t)b * Qn + qi) * DD + oc0);
        #pragma unroll
        for (int q4 = 0; q4 < 4; q4++) {
            float4 w;
            w.x = o[ii][q4 * 4 + 0] * inv;
            w.y = o[ii][q4 * 4 + 1] * inv;
            w.z = o[ii][q4 * 4 + 2] * inv;
            w.w = o[ii][q4 * 4 + 3] * inv;
            dst[q4] = w;
        }
    }
}

extern "C" void kernel_launch(void* const* d_in, const int* in_sizes, int n_in,
                              void* d_out, int out_size)
{
    const float* Q  = (const float*)d_in[0];
    const float* K  = (const float*)d_in[1];
    const float* V  = (const float*)d_in[2];
    const int*   vl = (const int*)d_in[3];

    const int B  = in_sizes[3];
    const int Qn = in_sizes[0] / (B * DD);
    const int Kn = in_sizes[1] / (B * DD);

    const size_t smem_bytes =
        (size_t)(BQ * QSTR + BK * KSTR + BK * DD + BK * PSTR + BQ) * sizeof(float);

    cudaFuncSetAttribute(attn_kernel,
                         cudaFuncAttributeMaxDynamicSharedMemorySize,
                         (int)smem_bytes);

    dim3 grid((Qn + BQ - 1) / BQ, B);
    attn_kernel<<<grid, NTH, smem_bytes>>>(Q, K, V, vl, (float*)d_out, Qn, Kn);
}

// round 4
// speedup vs baseline: 2.1102x; 2.1102x over previous
#include <cuda_runtime.h>
#include <cstdint>

// Fused masked SDPA via mma.sync tf32 (baseline PTX, works at compute_103).
// Pre-pass: transpose V into g_Vt[b][d][key] (tf32-rounded), 32MB scratch.
// Main: 8 warps x (16q x 64keys/tile); Q frags in regs; P stays in regs via
// shfl-based D-frag -> A-frag conversion; K / V^T B-frags via ldmatrix.

#define DD   128
#define BQ   128
#define BK   64
#define NTH  256
#define KSTR 132                  // Ks row stride (floats)
#define TSTR 68                   // VsT row stride (floats)
#define VOFFB (BK * KSTR * 4)     // VsT byte offset in smem
#define SMEMB (VOFFB + DD * TSTR * 4)

__device__ float g_Vt[16ull * 128ull * 4096ull];   // [B][d][key] tf32 bits

__device__ __forceinline__ uint32_t f2tf(float x) {
    uint32_t u; asm("cvt.rna.tf32.f32 %0, %1;" : "=r"(u) : "f"(x)); return u;
}

__device__ __forceinline__ uint32_t smem_u32(const void* p) {
    uint32_t a;
    asm("{ .reg .u64 t; cvta.to.shared.u64 t, %1; cvt.u32.u64 %0, t; }"
        : "=r"(a) : "l"(p));
    return a;
}

__device__ __forceinline__ void ldsm4(uint32_t* r, uint32_t addr) {
    asm volatile("ldmatrix.sync.aligned.m8n8.x4.shared.b16 {%0,%1,%2,%3}, [%4];"
                 : "=r"(r[0]), "=r"(r[1]), "=r"(r[2]), "=r"(r[3]) : "r"(addr));
}

__device__ __forceinline__ void mma8(float* d, const uint32_t* a,
                                     uint32_t b0, uint32_t b1) {
    asm volatile(
        "mma.sync.aligned.m16n8k8.row.col.f32.tf32.tf32.f32 "
        "{%0,%1,%2,%3}, {%4,%5,%6,%7}, {%8,%9}, {%0,%1,%2,%3};"
        : "+f"(d[0]), "+f"(d[1]), "+f"(d[2]), "+f"(d[3])
        : "r"(a[0]), "r"(a[1]), "r"(a[2]), "r"(a[3]), "r"(b0), "r"(b1));
}

// ---------------- V transpose pre-pass: Vg[b][key][d] -> g_Vt[b][d][key] ----
__global__ void vtrans(const float* __restrict__ Vg, int Kn) {
    __shared__ float tile[32][33];
    const int b  = blockIdx.z;
    const int k0 = blockIdx.x * 32;
    const int d0 = blockIdx.y * 32;
    const int tx = threadIdx.x, ty = threadIdx.y;

    const float* src = Vg + ((size_t)b * Kn + k0) * DD + d0;
    #pragma unroll
    for (int j = 0; j < 4; j++)
        tile[ty + 8 * j][tx] = src[(size_t)(ty + 8 * j) * DD + tx];
    __syncthreads();

    float* dst = g_Vt + ((size_t)b * DD + d0) * Kn + k0;
    #pragma unroll
    for (int j = 0; j < 4; j++) {
        float v = tile[tx][ty + 8 * j];
        dst[(size_t)(ty + 8 * j) * Kn + tx] = __uint_as_float(f2tf(v));
    }
}

// ---------------- main fused attention ----------------
__global__ __launch_bounds__(NTH, 1)
void attn_mma(const float* __restrict__ Qg, const float* __restrict__ Kg,
              const int* __restrict__ vlen, float* __restrict__ Og,
              int Qn, int Kn)
{
    extern __shared__ uint32_t smem[];          // Ks [64][132] ++ VsT [128][68]
    const uint32_t sbase = smem_u32(smem);

    const int tid  = threadIdx.x;
    const int w    = tid >> 5;
    const int lane = tid & 31;
    const int g    = lane >> 2;                 // group id (row within m16)
    const int t    = lane & 3;                  // thread-in-group
    const int b    = blockIdx.y;
    const int q0   = blockIdx.x * BQ;
    const int qb   = q0 + w * 16;               // this warp's 16 q-rows
    const int valid = vlen[b];
    const float scale = 0.088388347648318447f;  // 1/sqrt(128)
    const unsigned FULL = 0xFFFFFFFFu;

    // ldmatrix per-lane address components
    const int mrow   = lane & 7;
    const int mq     = lane >> 3;
    const int nb_off = mq >> 1;                  // which n8 of the pair
    const int half   = mq & 1;                   // k-half (cols 0-3 / 4-7)
    const uint32_t kA0 = sbase + ((uint32_t)((nb_off * 8 + mrow) * KSTR + half * 4) << 2);
    const uint32_t vA0 = sbase + VOFFB + ((uint32_t)((nb_off * 8 + mrow) * TSTR + half * 4) << 2);

    // ---- Q fragments in registers (scale + tf32 folded), loaded once ----
    uint32_t qf[16][4];
    {
        const float* qp = Qg + ((size_t)b * Qn + qb) * DD;
        #pragma unroll
        for (int s = 0; s < 16; s++) {
            const int c = s * 8 + t;
            qf[s][0] = f2tf(qp[(size_t)g * DD + c] * scale);
            qf[s][1] = f2tf(qp[(size_t)(g + 8) * DD + c] * scale);
            qf[s][2] = f2tf(qp[(size_t)g * DD + c + 4] * scale);
            qf[s][3] = f2tf(qp[(size_t)(g + 8) * DD + c + 4] * scale);
        }
    }

    float oacc[16][4];
    #pragma unroll
    for (int i = 0; i < 16; i++)
        { oacc[i][0] = oacc[i][1] = oacc[i][2] = oacc[i][3] = 0.f; }
    float lac0 = 0.f, lac1 = 0.f;

    const int ktiles = (valid + BK - 1) / BK;    // skip fully-masked tiles

    for (int kt = 0; kt < ktiles; kt++) {
        const int k0 = kt * BK;
        __syncthreads();

        // ---- stage K (cvt to tf32) and V^T (already tf32) into smem ----
        {
            const float4* kg = (const float4*)(Kg + ((size_t)b * Kn + k0) * DD);
            for (int i = tid; i < BK * 32; i += NTH) {
                float4 v = kg[i];
                uint4 u = make_uint4(f2tf(v.x), f2tf(v.y), f2tf(v.z), f2tf(v.w));
                *(uint4*)&smem[(i >> 5) * KSTR + (i & 31) * 4] = u;
            }
            for (int i = tid; i < DD * 16; i += NTH) {
                const int d = i >> 4, kc = i & 15;
                float4 v = *(const float4*)(g_Vt + ((size_t)(b * DD + d)) * Kn + k0 + kc * 4);
                *(float4*)&smem[VOFFB / 4 + d * TSTR + kc * 4] = v;
            }
        }
        __syncthreads();

        // ---- GEMM1: S(16x64) = Q . K^T ----
        float sacc[8][4];
        #pragma unroll
        for (int i = 0; i < 8; i++)
            { sacc[i][0] = sacc[i][1] = sacc[i][2] = sacc[i][3] = 0.f; }

        #pragma unroll
        for (int s = 0; s < 16; s++) {
            #pragma unroll
            for (int nbp = 0; nbp < 4; nbp++) {
                uint32_t kb[4];
                ldsm4(kb, kA0 + nbp * (16 * KSTR * 4) + s * 32);
                mma8(sacc[2 * nbp],     qf[s], kb[0], kb[1]);
                mma8(sacc[2 * nbp + 1], qf[s], kb[2], kb[3]);
            }
        }

        // ---- mask + exp + row-sums + tf32 P-fragments ----
        uint32_t pf[8][4];
        #pragma unroll
        for (int nb = 0; nb < 8; nb++) {
            const int c0 = k0 + nb * 8 + 2 * t;
            const bool m0 = c0 < valid, m1 = (c0 + 1) < valid;
            float p0 = m0 ? __expf(sacc[nb][0]) : 0.f;
            float p1 = m1 ? __expf(sacc[nb][1]) : 0.f;
            float p2 = m0 ? __expf(sacc[nb][2]) : 0.f;
            float p3 = m1 ? __expf(sacc[nb][3]) : 0.f;
            lac0 += p0 + p1;  lac1 += p2 + p3;
            pf[nb][0] = f2tf(p0); pf[nb][1] = f2tf(p1);
            pf[nb][2] = f2tf(p2); pf[nb][3] = f2tf(p3);
        }

        // ---- GEMM2: O(16x128) += P . V  (A via shfl D->A layout convert) ----
        const int s0l = (lane & ~3) | (t >> 1);
        const int s1l = s0l + 2;
        #pragma unroll
        for (int s2 = 0; s2 < 8; s2++) {
            uint32_t ap[4];
            {
                uint32_t x0 = __shfl_sync(FULL, pf[s2][0], s0l);
                uint32_t x1 = __shfl_sync(FULL, pf[s2][1], s0l);
                uint32_t y0 = __shfl_sync(FULL, pf[s2][0], s1l);
                uint32_t y1 = __shfl_sync(FULL, pf[s2][1], s1l);
                ap[0] = (t & 1) ? x1 : x0;       // (g,   key t)
                ap[2] = (t & 1) ? y1 : y0;       // (g,   key t+4)
                uint32_t z0 = __shfl_sync(FULL, pf[s2][2], s0l);
                uint32_t z1 = __shfl_sync(FULL, pf[s2][3], s0l);
                uint32_t w0 = __shfl_sync(FULL, pf[s2][2], s1l);
                uint32_t w1 = __shfl_sync(FULL, pf[s2][3], s1l);
                ap[1] = (t & 1) ? z1 : z0;       // (g+8, key t)
                ap[3] = (t & 1) ? w1 : w0;       // (g+8, key t+4)
            }
            #pragma unroll
            for (int nbp = 0; nbp < 8; nbp++) {
                uint32_t vb[4];
                ldsm4(vb, vA0 + nbp * (16 * TSTR * 4) + s2 * 32);
                mma8(oacc[2 * nbp],     ap, vb[0], vb[1]);
                mma8(oacc[2 * nbp + 1], ap, vb[2], vb[3]);
            }
        }
    }

    // ---- epilogue: reduce row sums in quad, normalize, store ----
    lac0 += __shfl_xor_sync(FULL, lac0, 1);
    lac0 += __shfl_xor_sync(FULL, lac0, 2);
    lac1 += __shfl_xor_sync(FULL, lac1, 1);
    lac1 += __shfl_xor_sync(FULL, lac1, 2);
    const float inv0 = 1.0f / lac0;
    const float inv1 = 1.0f / lac1;

    float2* o0 = (float2*)(Og + ((size_t)b * Qn + qb + g) * DD);
    float2* o1 = (float2*)(Og + ((size_t)b * Qn + qb + g + 8) * DD);
    #pragma unroll
    for (int nb = 0; nb < 16; nb++) {
        o0[nb * 4 + t] = make_float2(oacc[nb][0] * inv0, oacc[nb][1] * inv0);
        o1[nb * 4 + t] = make_float2(oacc[nb][2] * inv1, oacc[nb][3] * inv1);
    }
}

extern "C" void kernel_launch(void* const* d_in, const int* in_sizes, int n_in,
                              void* d_out, int out_size)
{
    const float* Q  = (const float*)d_in[0];
    const float* K  = (const float*)d_in[1];
    const float* V  = (const float*)d_in[2];
    const int*   vl = (const int*)d_in[3];

    const int B  = in_sizes[3];
    const int Qn = in_sizes[0] / (B * DD);
    const int Kn = in_sizes[1] / (B * DD);

    dim3 tg(Kn / 32, DD / 32, B);
    vtrans<<<tg, dim3(32, 8)>>>(V, Kn);

    cudaFuncSetAttribute(attn_mma, cudaFuncAttributeMaxDynamicSharedMemorySize,
                         SMEMB);
    dim3 grid(Qn / BQ, B);
    attn_mma<<<grid, NTH, SMEMB>>>(Q, K, vl, (float*)d_out, Qn, Kn);
}

// round 5
// speedup vs baseline: 3.9675x; 1.8801x over previous
#include <cuda_runtime.h>
#include <cstdint>

// Fused masked SDPA via mma.sync tf32 (baseline PTX, works at compute_103).
// Pre-pass 1: K -> g_Kc  (tf32-rounded, same layout)        ~16us
// Pre-pass 2: V -> g_Vt  (transposed [b][d][key], tf32)     ~16us
// Main: 8 warps x (16q x 64keys/tile); Q frags in regs; P stays in regs via
// shfl D-frag->A-frag; K / V^T via ldmatrix; cp.async double-buffered tiles.

#define DD   128
#define BQ   128
#define BK   64
#define NTH  256
#define KSTR 132                  // Ks row stride (floats)
#define TSTR 68                   // VsT row stride (floats)
#define VOFFB (BK * KSTR * 4)     // VsT byte offset within one buffer
#define BUFB  (VOFFB + DD * TSTR * 4)   // one buffer: 68608 B
#define SMEMB (2 * BUFB)                // 137216 B

__device__ float g_Vt[16ull * 128ull * 4096ull];   // [B][d][key] tf32 bits
__device__ float g_Kc[16ull * 4096ull * 128ull];   // [B][key][d] tf32 bits

__device__ __forceinline__ uint32_t f2tf(float x) {
    uint32_t u; asm("cvt.rna.tf32.f32 %0, %1;" : "=r"(u) : "f"(x)); return u;
}

__device__ __forceinline__ uint32_t smem_u32(const void* p) {
    uint32_t a;
    asm("{ .reg .u64 t; cvta.to.shared.u64 t, %1; cvt.u32.u64 %0, t; }"
        : "=r"(a) : "l"(p));
    return a;
}

__device__ __forceinline__ void ldsm4(uint32_t* r, uint32_t addr) {
    asm volatile("ldmatrix.sync.aligned.m8n8.x4.shared.b16 {%0,%1,%2,%3}, [%4];"
                 : "=r"(r[0]), "=r"(r[1]), "=r"(r[2]), "=r"(r[3]) : "r"(addr));
}

__device__ __forceinline__ void mma8(float* d, const uint32_t* a,
                                     uint32_t b0, uint32_t b1) {
    asm volatile(
        "mma.sync.aligned.m16n8k8.row.col.f32.tf32.tf32.f32 "
        "{%0,%1,%2,%3}, {%4,%5,%6,%7}, {%8,%9}, {%0,%1,%2,%3};"
        : "+f"(d[0]), "+f"(d[1]), "+f"(d[2]), "+f"(d[3])
        : "r"(a[0]), "r"(a[1]), "r"(a[2]), "r"(a[3]), "r"(b0), "r"(b1));
}

__device__ __forceinline__ void cpa16(uint32_t dst, const void* src) {
    asm volatile("cp.async.cg.shared.global [%0], [%1], 16;"
                 :: "r"(dst), "l"(src) : "memory");
}
#define CPA_COMMIT() asm volatile("cp.async.commit_group;" ::: "memory")
#define CPA_WAIT(n)  asm volatile("cp.async.wait_group %0;" :: "n"(n) : "memory")

// ---------------- pre-pass 1: K -> tf32-rounded copy ----------------
__global__ void kconv(const float* __restrict__ Kg, size_t n4) {
    size_t i = (size_t)blockIdx.x * blockDim.x + threadIdx.x;
    if (i < n4) {
        float4 v = ((const float4*)Kg)[i];
        ((uint4*)g_Kc)[i] = make_uint4(f2tf(v.x), f2tf(v.y), f2tf(v.z), f2tf(v.w));
    }
}

// ---------------- pre-pass 2: V -> g_Vt[b][d][key] (tf32) ----------------
__global__ void vtrans(const float* __restrict__ Vg, int Kn) {
    __shared__ float tile[32][33];
    const int b  = blockIdx.z;
    const int k0 = blockIdx.x * 32;
    const int d0 = blockIdx.y * 32;
    const int tx = threadIdx.x, ty = threadIdx.y;

    const float* src = Vg + ((size_t)b * Kn + k0) * DD + d0;
    #pragma unroll
    for (int j = 0; j < 4; j++)
        tile[ty + 8 * j][tx] = src[(size_t)(ty + 8 * j) * DD + tx];
    __syncthreads();

    float* dst = g_Vt + ((size_t)b * DD + d0) * Kn + k0;
    #pragma unroll
    for (int j = 0; j < 4; j++) {
        float v = tile[tx][ty + 8 * j];
        dst[(size_t)(ty + 8 * j) * Kn + tx] = __uint_as_float(f2tf(v));
    }
}

// ---------------- main fused attention ----------------
__global__ __launch_bounds__(NTH, 1)
void attn_mma(const float* __restrict__ Qg, const int* __restrict__ vlen,
              float* __restrict__ Og, int Qn, int Kn)
{
    extern __shared__ uint32_t smem[];   // 2 x (Ks [64][132] ++ VsT [128][68])
    const uint32_t sbase = smem_u32(smem);

    const int tid  = threadIdx.x;
    const int w    = tid >> 5;
    const int lane = tid & 31;
    const int g    = lane >> 2;                 // row within m16 group
    const int t    = lane & 3;                  // thread-in-group
    const int b    = blockIdx.y;
    const int q0   = blockIdx.x * BQ;
    const int qb   = q0 + w * 16;               // this warp's 16 q-rows
    const int valid = vlen[b];
    const float scale = 0.088388347648318447f;  // 1/sqrt(128)
    const unsigned FULL = 0xFFFFFFFFu;

    // ldmatrix per-lane address components
    const int mrow   = lane & 7;
    const int mq     = lane >> 3;
    const int nb_off = mq >> 1;                  // which n8 of the pair
    const int half   = mq & 1;                   // k-half (cols 0-3 / 4-7)
    const uint32_t kA0 = sbase + ((uint32_t)((nb_off * 8 + mrow) * KSTR + half * 4) << 2);
    const uint32_t vA0 = sbase + VOFFB + ((uint32_t)((nb_off * 8 + mrow) * TSTR + half * 4) << 2);

    // per-thread cp.async slots: 8 K chunks + 8 V chunks (16B each)
    //   K: chunk index c in [0,8): linear idx = tid + 256*c over 2048 float4
    //   V: chunk index c in [0,8): linear idx = tid + 256*c over 1024*... (DD*16=2048? no: DD*16=2048/2)
    // K: 64*32 = 2048 float4 -> 8 per thread.  V: 128*16 = 2048 float4 -> 8 per thread.
    const float* kcb = g_Kc + (size_t)b * Kn * DD;
    const float* vtb = g_Vt + (size_t)b * DD * Kn;

    // ---- Q fragments in registers (scale + tf32 folded), loaded once ----
    uint32_t qf[16][4];
    {
        const float* qp = Qg + ((size_t)b * Qn + qb) * DD;
        #pragma unroll
        for (int s = 0; s < 16; s++) {
            const int c = s * 8 + t;
            qf[s][0] = f2tf(qp[(size_t)g * DD + c] * scale);
            qf[s][1] = f2tf(qp[(size_t)(g + 8) * DD + c] * scale);
            qf[s][2] = f2tf(qp[(size_t)g * DD + c + 4] * scale);
            qf[s][3] = f2tf(qp[(size_t)(g + 8) * DD + c + 4] * scale);
        }
    }

    float oacc[16][4];
    #pragma unroll
    for (int i = 0; i < 16; i++)
        { oacc[i][0] = oacc[i][1] = oacc[i][2] = oacc[i][3] = 0.f; }
    float lac0 = 0.f, lac1 = 0.f;

    const int ktiles = (valid + BK - 1) / BK;    // skip fully-masked tiles

    // ---- tile loader: K tile [64][128] + V^T tile [128][64] into buffer ----
    auto load_tile = [&](int kt, int buf) {
        const uint32_t bb = sbase + (uint32_t)buf * BUFB;
        const int k0 = kt * BK;
        #pragma unroll
        for (int c = 0; c < 8; c++) {
            const int idx = tid + NTH * c;             // 0..2047
            const int r = idx >> 5, c4 = idx & 31;
            cpa16(bb + ((uint32_t)(r * KSTR + c4 * 4) << 2),
                  kcb + ((size_t)(k0 + r) * DD + c4 * 4));
        }
        #pragma unroll
        for (int c = 0; c < 8; c++) {
            const int idx = tid + NTH * c;             // 0..2047
            const int d = idx >> 4, kc = idx & 15;
            cpa16(bb + VOFFB + ((uint32_t)(d * TSTR + kc * 4) << 2),
                  vtb + ((size_t)d * Kn + k0 + kc * 4));
        }
    };

    load_tile(0, 0);
    CPA_COMMIT();

    int buf = 0;
    for (int kt = 0; kt < ktiles; kt++) {
        const int k0 = kt * BK;

        if (kt + 1 < ktiles) {
            load_tile(kt + 1, buf ^ 1);
            CPA_COMMIT();
            CPA_WAIT(1);
        } else {
            CPA_WAIT(0);
        }
        __syncthreads();

        const uint32_t boff = (uint32_t)buf * BUFB;

        // ---- GEMM1: S(16x64) = Q . K^T ----
        float sacc[8][4];
        #pragma unroll
        for (int i = 0; i < 8; i++)
            { sacc[i][0] = sacc[i][1] = sacc[i][2] = sacc[i][3] = 0.f; }

        #pragma unroll
        for (int s = 0; s < 16; s++) {
            #pragma unroll
            for (int nbp = 0; nbp < 4; nbp++) {
                uint32_t kb[4];
                ldsm4(kb, kA0 + boff + nbp * (16 * KSTR * 4) + s * 32);
                mma8(sacc[2 * nbp],     qf[s], kb[0], kb[1]);
                mma8(sacc[2 * nbp + 1], qf[s], kb[2], kb[3]);
            }
        }

        // ---- mask + exp + row-sums + tf32 P-fragments ----
        uint32_t pf[8][4];
        #pragma unroll
        for (int nb = 0; nb < 8; nb++) {
            const int c0 = k0 + nb * 8 + 2 * t;
            const bool m0 = c0 < valid, m1 = (c0 + 1) < valid;
            float p0 = m0 ? __expf(sacc[nb][0]) : 0.f;
            float p1 = m1 ? __expf(sacc[nb][1]) : 0.f;
            float p2 = m0 ? __expf(sacc[nb][2]) : 0.f;
            float p3 = m1 ? __expf(sacc[nb][3]) : 0.f;
            lac0 += p0 + p1;  lac1 += p2 + p3;
            pf[nb][0] = f2tf(p0); pf[nb][1] = f2tf(p1);
            pf[nb][2] = f2tf(p2); pf[nb][3] = f2tf(p3);
        }

        // ---- GEMM2: O(16x128) += P . V  (A via shfl D->A layout convert) ----
        const int s0l = (lane & ~3) | (t >> 1);
        const int s1l = s0l + 2;
        #pragma unroll
        for (int s2 = 0; s2 < 8; s2++) {
            uint32_t ap[4];
            {
                uint32_t x0 = __shfl_sync(FULL, pf[s2][0], s0l);
                uint32_t x1 = __shfl_sync(FULL, pf[s2][1], s0l);
                uint32_t y0 = __shfl_sync(FULL, pf[s2][0], s1l);
                uint32_t y1 = __shfl_sync(FULL, pf[s2][1], s1l);
                ap[0] = (t & 1) ? x1 : x0;       // (g,   key t)
                ap[2] = (t & 1) ? y1 : y0;       // (g,   key t+4)
                uint32_t z0 = __shfl_sync(FULL, pf[s2][2], s0l);
                uint32_t z1 = __shfl_sync(FULL, pf[s2][3], s0l);
                uint32_t w0 = __shfl_sync(FULL, pf[s2][2], s1l);
                uint32_t w1 = __shfl_sync(FULL, pf[s2][3], s1l);
                ap[1] = (t & 1) ? z1 : z0;       // (g+8, key t)
                ap[3] = (t & 1) ? w1 : w0;       // (g+8, key t+4)
            }
            #pragma unroll
            for (int nbp = 0; nbp < 8; nbp++) {
                uint32_t vb[4];
                ldsm4(vb, vA0 + boff + nbp * (16 * TSTR * 4) + s2 * 32);
                mma8(oacc[2 * nbp],     ap, vb[0], vb[1]);
                mma8(oacc[2 * nbp + 1], ap, vb[2], vb[3]);
            }
        }

        __syncthreads();        // buf reusable: next-next cp.async may overwrite
        buf ^= 1;
    }

    // ---- epilogue: reduce row sums in quad, normalize, store ----
    lac0 += __shfl_xor_sync(FULL, lac0, 1);
    lac0 += __shfl_xor_sync(FULL, lac0, 2);
    lac1 += __shfl_xor_sync(FULL, lac1, 1);
    lac1 += __shfl_xor_sync(FULL, lac1, 2);
    const float inv0 = 1.0f / lac0;
    const float inv1 = 1.0f / lac1;

    float2* o0 = (float2*)(Og + ((size_t)b * Qn + qb + g) * DD);
    float2* o1 = (float2*)(Og + ((size_t)b * Qn + qb + g + 8) * DD);
    #pragma unroll
    for (int nb = 0; nb < 16; nb++) {
        o0[nb * 4 + t] = make_float2(oacc[nb][0] * inv0, oacc[nb][1] * inv0);
        o1[nb * 4 + t] = make_float2(oacc[nb][2] * inv1, oacc[nb][3] * inv1);
    }
}

extern "C" void kernel_launch(void* const* d_in, const int* in_sizes, int n_in,
                              void* d_out, int out_size)
{
    const float* Q  = (const float*)d_in[0];
    const float* K  = (const float*)d_in[1];
    const float* V  = (const float*)d_in[2];
    const int*   vl = (const int*)d_in[3];

    const int B  = in_sizes[3];
    const int Qn = in_sizes[0] / (B * DD);
    const int Kn = in_sizes[1] / (B * DD);

    const size_t n4 = (size_t)B * Kn * DD / 4;
    kconv<<<(unsigned)((n4 + 255) / 256), 256>>>(K, n4);

    dim3 tg(Kn / 32, DD / 32, B);
    vtrans<<<tg, dim3(32, 8)>>>(V, Kn);

    cudaFuncSetAttribute(attn_mma, cudaFuncAttributeMaxDynamicSharedMemorySize,
                         SMEMB);
    dim3 grid(Qn / BQ, B);
    attn_mma<<<grid, NTH, SMEMB>>>(Q, vl, (float*)d_out, Qn, Kn);
}

// round 7
// speedup vs baseline: 4.0464x; 1.0199x over previous
#include <cuda_runtime.h>
#include <cstdint>

// Fused masked SDPA via mma.sync tf32 (baseline PTX, works at compute_103).
// Pre-pass 1: K -> g_Kc (tf32-rounded). Pre-pass 2: V -> g_Vt (transposed).
// sched: sort batches by valid_len desc (LPT), reset work counter.
// Main: persistent CTAs popping (batch, qblock) units from a global queue;
// per unit: 8 warps x (16q x 64keys/tile), Q frags in regs, P in regs via
// shfl D->A convert, K/V^T via ldmatrix, cp.async double-buffered tiles.

#define DD   128
#define BQ   128
#define BK   64
#define NTH  256
#define KSTR 132                  // Ks row stride (floats)
#define TSTR 68                   // VsT row stride (floats)
#define VOFFB (BK * KSTR * 4)     // VsT byte offset within one buffer
#define BUFB  (VOFFB + DD * TSTR * 4)   // one buffer: 68608 B
#define SMEMB (2 * BUFB + 16)           // + work-id slot
#define WSLOT (2 * BUFB / 4)            // uint32 index of work-id slot

__device__ float g_Vt[16ull * 128ull * 4096ull];   // [B][d][key] tf32 bits
__device__ float g_Kc[16ull * 4096ull * 128ull];   // [B][key][d] tf32 bits
__device__ int   g_next;
__device__ int   g_order[64];

__device__ __forceinline__ uint32_t f2tf(float x) {
    uint32_t u; asm("cvt.rna.tf32.f32 %0, %1;" : "=r"(u) : "f"(x)); return u;
}

__device__ __forceinline__ uint32_t smem_u32(const void* p) {
    uint32_t a;
    asm("{ .reg .u64 t; cvta.to.shared.u64 t, %1; cvt.u32.u64 %0, t; }"
        : "=r"(a) : "l"(p));
    return a;
}

__device__ __forceinline__ void ldsm4(uint32_t* r, uint32_t addr) {
    asm volatile("ldmatrix.sync.aligned.m8n8.x4.shared.b16 {%0,%1,%2,%3}, [%4];"
                 : "=r"(r[0]), "=r"(r[1]), "=r"(r[2]), "=r"(r[3]) : "r"(addr));
}

__device__ __forceinline__ void mma8(float* d, const uint32_t* a,
                                     uint32_t b0, uint32_t b1) {
    asm volatile(
        "mma.sync.aligned.m16n8k8.row.col.f32.tf32.tf32.f32 "
        "{%0,%1,%2,%3}, {%4,%5,%6,%7}, {%8,%9}, {%0,%1,%2,%3};"
        : "+f"(d[0]), "+f"(d[1]), "+f"(d[2]), "+f"(d[3])
        : "r"(a[0]), "r"(a[1]), "r"(a[2]), "r"(a[3]), "r"(b0), "r"(b1));
}

__device__ __forceinline__ void cpa16(uint32_t dst, const void* src) {
    asm volatile("cp.async.cg.shared.global [%0], [%1], 16;"
                 :: "r"(dst), "l"(src) : "memory");
}
#define CPA_COMMIT() asm volatile("cp.async.commit_group;" ::: "memory")
#define CPA_WAIT(n)  asm volatile("cp.async.wait_group %0;" :: "n"(n) : "memory")

// ---------------- pre-pass 1: K -> tf32-rounded copy ----------------
__global__ void kconv(const float* __restrict__ Kg, size_t n4) {
    size_t i = (size_t)blockIdx.x * blockDim.x + threadIdx.x;
    if (i < n4) {
        float4 v = ((const float4*)Kg)[i];
        ((uint4*)g_Kc)[i] = make_uint4(f2tf(v.x), f2tf(v.y), f2tf(v.z), f2tf(v.w));
    }
}

// ---------------- pre-pass 2: V -> g_Vt[b][d][key] (tf32) ----------------
__global__ void vtrans(const float* __restrict__ Vg, int Kn) {
    __shared__ float tile[32][33];
    const int b  = blockIdx.z;
    const int k0 = blockIdx.x * 32;
    const int d0 = blockIdx.y * 32;
    const int tx = threadIdx.x, ty = threadIdx.y;

    const float* src = Vg + ((size_t)b * Kn + k0) * DD + d0;
    #pragma unroll
    for (int j = 0; j < 4; j++)
        tile[ty + 8 * j][tx] = src[(size_t)(ty + 8 * j) * DD + tx];
    __syncthreads();

    float* dst = g_Vt + ((size_t)b * DD + d0) * Kn + k0;
    #pragma unroll
    for (int j = 0; j < 4; j++) {
        float v = tile[tx][ty + 8 * j];
        dst[(size_t)(ty + 8 * j) * Kn + tx] = __uint_as_float(f2tf(v));
    }
}

// ---------------- scheduler: LPT batch order + counter reset ----------------
__global__ void sched(const int* __restrict__ vlen, int B) {
    if (threadIdx.x == 0) {
        int idx[64], vl[64];
        for (int i = 0; i < B; i++) { idx[i] = i; vl[i] = vlen[i]; }
        for (int i = 1; i < B; i++) {           // insertion sort desc, stable
            int vi = vl[i], ii = idx[i], j = i - 1;
            while (j >= 0 && vl[j] < vi) {
                vl[j + 1] = vl[j]; idx[j + 1] = idx[j]; j--;
            }
            vl[j + 1] = vi; idx[j + 1] = ii;
        }
        for (int i = 0; i < B; i++) g_order[i] = idx[i];
        g_next = 0;
    }
}

// ---------------- main fused attention (persistent) ----------------
__global__ __launch_bounds__(NTH, 1)
void attn_mma(const float* __restrict__ Qg, const int* __restrict__ vlen,
              float* __restrict__ Og, int Qn, int Kn, int nq, int nunits)
{
    extern __shared__ uint32_t smem[];   // 2 x (Ks [64][132] ++ VsT [128][68])
    const uint32_t sbase = smem_u32(smem);

    const int tid  = threadIdx.x;
    const int w    = tid >> 5;
    const int lane = tid & 31;
    const int g    = lane >> 2;                 // row within m16 group
    const int t    = lane & 3;                  // thread-in-group
    const float scale = 0.088388347648318447f;  // 1/sqrt(128)
    const unsigned FULL = 0xFFFFFFFFu;

    // ldmatrix per-lane address components
    const int mrow   = lane & 7;
    const int mq     = lane >> 3;
    const int nb_off = mq >> 1;                  // which n8 of the pair
    const int half   = mq & 1;                   // k-half (cols 0-3 / 4-7)
    const uint32_t kA0 = sbase + ((uint32_t)((nb_off * 8 + mrow) * KSTR + half * 4) << 2);
    const uint32_t vA0 = sbase + VOFFB + ((uint32_t)((nb_off * 8 + mrow) * TSTR + half * 4) << 2);

    const int s0l = (lane & ~3) | (t >> 1);
    const int s1l = s0l + 2;

    for (;;) {
        // ---- pop next work unit ----
        if (tid == 0) smem[WSLOT] = (uint32_t)atomicAdd(&g_next, 1);
        __syncthreads();
        const int u = (int)smem[WSLOT];
        if (u >= nunits) break;

        const int b     = g_order[u / nq];
        const int qb    = (u % nq) * BQ + w * 16;    // this warp's 16 q-rows
        const int valid = vlen[b];

        const float* kcb = g_Kc + (size_t)b * Kn * DD;
        const float* vtb = g_Vt + (size_t)b * DD * Kn;

        // ---- Q fragments in registers (scale + tf32 folded) ----
        uint32_t qf[16][4];
        {
            const float* qp = Qg + ((size_t)b * Qn + qb) * DD;
            #pragma unroll
            for (int s = 0; s < 16; s++) {
                const int c = s * 8 + t;
                qf[s][0] = f2tf(qp[(size_t)g * DD + c] * scale);
                qf[s][1] = f2tf(qp[(size_t)(g + 8) * DD + c] * scale);
                qf[s][2] = f2tf(qp[(size_t)g * DD + c + 4] * scale);
                qf[s][3] = f2tf(qp[(size_t)(g + 8) * DD + c + 4] * scale);
            }
        }

        float oacc[16][4];
        #pragma unroll
        for (int i = 0; i < 16; i++)
            { oacc[i][0] = oacc[i][1] = oacc[i][2] = oacc[i][3] = 0.f; }
        float lac0 = 0.f, lac1 = 0.f;

        const int ktiles = (valid + BK - 1) / BK;

        auto load_tile = [&](int kt, int bf) {
            const uint32_t bb = sbase + (uint32_t)bf * BUFB;
            const int k0 = kt * BK;
            #pragma unroll
            for (int c = 0; c < 8; c++) {
                const int idx = tid + NTH * c;             // 0..2047
                const int r = idx >> 5, c4 = idx & 31;
                cpa16(bb + ((uint32_t)(r * KSTR + c4 * 4) << 2),
                      kcb + ((size_t)(k0 + r) * DD + c4 * 4));
            }
            #pragma unroll
            for (int c = 0; c < 8; c++) {
                const int idx = tid + NTH * c;             // 0..2047
                const int d = idx >> 4, kc = idx & 15;
                cpa16(bb + VOFFB + ((uint32_t)(d * TSTR + kc * 4) << 2),
                      vtb + ((size_t)d * Kn + k0 + kc * 4));
            }
        };

        load_tile(0, 0);
        CPA_COMMIT();

        int buf = 0;
        for (int kt = 0; kt < ktiles; kt++) {
            const int k0 = kt * BK;

            if (kt + 1 < ktiles) {
                load_tile(kt + 1, buf ^ 1);
                CPA_COMMIT();
                CPA_WAIT(1);
            } else {
                CPA_WAIT(0);
            }
            __syncthreads();

            const uint32_t boff = (uint32_t)buf * BUFB;

            // ---- GEMM1: S(16x64) = Q . K^T ----
            float sacc[8][4];
            #pragma unroll
            for (int i = 0; i < 8; i++)
                { sacc[i][0] = sacc[i][1] = sacc[i][2] = sacc[i][3] = 0.f; }

            #pragma unroll
            for (int s = 0; s < 16; s++) {
                #pragma unroll
                for (int nbp = 0; nbp < 4; nbp++) {
                    uint32_t kb[4];
                    ldsm4(kb, kA0 + boff + nbp * (16 * KSTR * 4) + s * 32);
                    mma8(sacc[2 * nbp],     qf[s], kb[0], kb[1]);
                    mma8(sacc[2 * nbp + 1], qf[s], kb[2], kb[3]);
                }
            }

            // ---- mask + exp + row-sums + tf32 P-fragments ----
            uint32_t pf[8][4];
            #pragma unroll
            for (int nb = 0; nb < 8; nb++) {
                const int c0 = k0 + nb * 8 + 2 * t;
                const bool m0 = c0 < valid, m1 = (c0 + 1) < valid;
                float p0 = m0 ? __expf(sacc[nb][0]) : 0.f;
                float p1 = m1 ? __expf(sacc[nb][1]) : 0.f;
                float p2 = m0 ? __expf(sacc[nb][2]) : 0.f;
                float p3 = m1 ? __expf(sacc[nb][3]) : 0.f;
                lac0 += p0 + p1;  lac1 += p2 + p3;
                pf[nb][0] = f2tf(p0); pf[nb][1] = f2tf(p1);
                pf[nb][2] = f2tf(p2); pf[nb][3] = f2tf(p3);
            }

            // ---- GEMM2: O(16x128) += P . V  (shfl D->A convert) ----
            #pragma unroll
            for (int s2 = 0; s2 < 8; s2++) {
                uint32_t ap[4];
                {
                    uint32_t x0 = __shfl_sync(FULL, pf[s2][0], s0l);
                    uint32_t x1 = __shfl_sync(FULL, pf[s2][1], s0l);
                    uint32_t y0 = __shfl_sync(FULL, pf[s2][0], s1l);
                    uint32_t y1 = __shfl_sync(FULL, pf[s2][1], s1l);
                    ap[0] = (t & 1) ? x1 : x0;       // (g,   key t)
                    ap[2] = (t & 1) ? y1 : y0;       // (g,   key t+4)
                    uint32_t z0 = __shfl_sync(FULL, pf[s2][2], s0l);
                    uint32_t z1 = __shfl_sync(FULL, pf[s2][3], s0l);
                    uint32_t w0 = __shfl_sync(FULL, pf[s2][2], s1l);
                    uint32_t w1 = __shfl_sync(FULL, pf[s2][3], s1l);
                    ap[1] = (t & 1) ? z1 : z0;       // (g+8, key t)
                    ap[3] = (t & 1) ? w1 : w0;       // (g+8, key t+4)
                }
                #pragma unroll
                for (int nbp = 0; nbp < 8; nbp++) {
                    uint32_t vb[4];
                    ldsm4(vb, vA0 + boff + nbp * (16 * TSTR * 4) + s2 * 32);
                    mma8(oacc[2 * nbp],     ap, vb[0], vb[1]);
                    mma8(oacc[2 * nbp + 1], ap, vb[2], vb[3]);
                }
            }

            __syncthreads();    // buffer reusable before next-next cp.async
            buf ^= 1;
        }

        // ---- epilogue: reduce row sums in quad, normalize, store ----
        float l0 = lac0, l1 = lac1;
        l0 += __shfl_xor_sync(FULL, l0, 1);
        l0 += __shfl_xor_sync(FULL, l0, 2);
        l1 += __shfl_xor_sync(FULL, l1, 1);
        l1 += __shfl_xor_sync(FULL, l1, 2);
        const float inv0 = 1.0f / l0;
        const float inv1 = 1.0f / l1;

        float2* o0 = (float2*)(Og + ((size_t)b * Qn + qb + g) * DD);
        float2* o1 = (float2*)(Og + ((size_t)b * Qn + qb + g + 8) * DD);
        #pragma unroll
        for (int nb = 0; nb < 16; nb++) {
            o0[nb * 4 + t] = make_float2(oacc[nb][0] * inv0, oacc[nb][1] * inv0);
            o1[nb * 4 + t] = make_float2(oacc[nb][2] * inv1, oacc[nb][3] * inv1);
        }
    }
}

extern "C" void kernel_launch(void* const* d_in, const int* in_sizes, int n_in,
                              void* d_out, int out_size)
{
    const float* Q  = (const float*)d_in[0];
    const float* K  = (const float*)d_in[1];
    const float* V  = (const float*)d_in[2];
    const int*   vl = (const int*)d_in[3];

    const int B  = in_sizes[3];
    const int Qn = in_sizes[0] / (B * DD);
    const int Kn = in_sizes[1] / (B * DD);
    const int nq = Qn / BQ;
    const int nunits = B * nq;

    const size_t n4 = (size_t)B * Kn * DD / 4;
    kconv<<<(unsigned)((n4 + 255) / 256), 256>>>(K, n4);

    dim3 tg(Kn / 32, DD / 32, B);
    vtrans<<<tg, dim3(32, 8)>>>(V, Kn);

    sched<<<1, 32>>>(vl, B);

    int dev = 0, nsm = 148;
    cudaGetDevice(&dev);
    cudaDeviceGetAttribute(&nsm, cudaDevAttrMultiProcessorCount, dev);
    if (nsm > nunits) nsm = nunits;

    cudaFuncSetAttribute(attn_mma, cudaFuncAttributeMaxDynamicSharedMemorySize,
                         SMEMB);
    attn_mma<<<nsm, NTH, SMEMB>>>(Q, vl, (float*)d_out, Qn, Kn, nq, nunits);
}

// round 8
// speedup vs baseline: 5.8180x; 1.4378x over previous
#include <cuda_runtime.h>
#include <cuda_fp16.h>
#include <cstdint>

// Fused masked SDPA: GEMM1 = mma.sync tf32 (Q,K), GEMM2 = mma.sync fp16 (P,V).
// fp16 A-frag layout == S D-frag layout -> P needs NO shuffles, just packs.
// Pre-pass 1: K -> g_Kc (tf32-rounded). Pre-pass 2: V -> g_Vt (fp16, transposed).
// sched: LPT batch order. Main: persistent CTAs, cp.async double-buffered.

#define DD   128
#define BQ   128
#define BK   64
#define NTH  256
#define KSTR 132                        // K smem row stride (floats)
#define VSTRB 144                       // V^T smem row stride (bytes, 72 halfs)
#define VOFFB (BK * KSTR * 4)           // 33792: V^T offset within buffer
#define BUFB  (VOFFB + DD * VSTRB)      // 52224 B per buffer
#define SMEMB (2 * BUFB + 16)
#define WSLOT (2 * BUFB / 4)

__device__ __half g_Vt[16ull * 128ull * 4096ull];  // [B][d][key] fp16
__device__ float  g_Kc[16ull * 4096ull * 128ull];  // [B][key][d] tf32 bits
__device__ int    g_next;
__device__ int    g_order[64];

__device__ __forceinline__ uint32_t f2tf(float x) {
    uint32_t u; asm("cvt.rna.tf32.f32 %0, %1;" : "=r"(u) : "f"(x)); return u;
}

__device__ __forceinline__ uint32_t smem_u32(const void* p) {
    uint32_t a;
    asm("{ .reg .u64 t; cvta.to.shared.u64 t, %1; cvt.u32.u64 %0, t; }"
        : "=r"(a) : "l"(p));
    return a;
}

__device__ __forceinline__ void ldsm4(uint32_t* r, uint32_t addr) {
    asm volatile("ldmatrix.sync.aligned.m8n8.x4.shared.b16 {%0,%1,%2,%3}, [%4];"
                 : "=r"(r[0]), "=r"(r[1]), "=r"(r[2]), "=r"(r[3]) : "r"(addr));
}

__device__ __forceinline__ void mma8(float* d, const uint32_t* a,
                                     uint32_t b0, uint32_t b1) {
    asm volatile(
        "mma.sync.aligned.m16n8k8.row.col.f32.tf32.tf32.f32 "
        "{%0,%1,%2,%3}, {%4,%5,%6,%7}, {%8,%9}, {%0,%1,%2,%3};"
        : "+f"(d[0]), "+f"(d[1]), "+f"(d[2]), "+f"(d[3])
        : "r"(a[0]), "r"(a[1]), "r"(a[2]), "r"(a[3]), "r"(b0), "r"(b1));
}

__device__ __forceinline__ void mma16h(float* d, const uint32_t* a,
                                       uint32_t b0, uint32_t b1) {
    asm volatile(
        "mma.sync.aligned.m16n8k16.row.col.f32.f16.f16.f32 "
        "{%0,%1,%2,%3}, {%4,%5,%6,%7}, {%8,%9}, {%0,%1,%2,%3};"
        : "+f"(d[0]), "+f"(d[1]), "+f"(d[2]), "+f"(d[3])
        : "r"(a[0]), "r"(a[1]), "r"(a[2]), "r"(a[3]), "r"(b0), "r"(b1));
}

__device__ __forceinline__ void cpa16(uint32_t dst, const void* src) {
    asm volatile("cp.async.cg.shared.global [%0], [%1], 16;"
                 :: "r"(dst), "l"(src) : "memory");
}
#define CPA_COMMIT() asm volatile("cp.async.commit_group;" ::: "memory")
#define CPA_WAIT(n)  asm volatile("cp.async.wait_group %0;" :: "n"(n) : "memory")

// ---------------- pre-pass 1: K -> tf32-rounded copy ----------------
__global__ void kconv(const float* __restrict__ Kg, size_t n4) {
    size_t i = (size_t)blockIdx.x * blockDim.x + threadIdx.x;
    if (i < n4) {
        float4 v = ((const float4*)Kg)[i];
        ((uint4*)g_Kc)[i] = make_uint4(f2tf(v.x), f2tf(v.y), f2tf(v.z), f2tf(v.w));
    }
}

// ---------------- pre-pass 2: V -> g_Vt[b][d][key] (fp16) ----------------
__global__ void vtrans(const float* __restrict__ Vg, int Kn) {
    __shared__ float tile[32][33];
    const int b  = blockIdx.z;
    const int k0 = blockIdx.x * 32;
    const int d0 = blockIdx.y * 32;
    const int tx = threadIdx.x, ty = threadIdx.y;

    const float* src = Vg + ((size_t)b * Kn + k0) * DD + d0;
    #pragma unroll
    for (int j = 0; j < 4; j++)
        tile[ty + 8 * j][tx] = src[(size_t)(ty + 8 * j) * DD + tx];
    __syncthreads();

    __half* dst = g_Vt + ((size_t)b * DD + d0) * Kn + k0;
    #pragma unroll
    for (int j = 0; j < 4; j++)
        dst[(size_t)(ty + 8 * j) * Kn + tx] = __float2half_rn(tile[tx][ty + 8 * j]);
}

// ---------------- scheduler: LPT batch order + counter reset ----------------
__global__ void sched(const int* __restrict__ vlen, int B) {
    if (threadIdx.x == 0) {
        int idx[64], vl[64];
        for (int i = 0; i < B; i++) { idx[i] = i; vl[i] = vlen[i]; }
        for (int i = 1; i < B; i++) {           // insertion sort desc, stable
            int vi = vl[i], ii = idx[i], j = i - 1;
            while (j >= 0 && vl[j] < vi) {
                vl[j + 1] = vl[j]; idx[j + 1] = idx[j]; j--;
            }
            vl[j + 1] = vi; idx[j + 1] = ii;
        }
        for (int i = 0; i < B; i++) g_order[i] = idx[i];
        g_next = 0;
    }
}

// ---------------- main fused attention (persistent) ----------------
__global__ __launch_bounds__(NTH, 1)
void attn_mma(const float* __restrict__ Qg, const int* __restrict__ vlen,
              float* __restrict__ Og, int Qn, int Kn, int nq, int nunits)
{
    extern __shared__ uint32_t smem[];  // 2 x (K [64][132]f32 ++ V^T [128][72]f16)
    const uint32_t sbase = smem_u32(smem);

    const int tid  = threadIdx.x;
    const int w    = tid >> 5;
    const int lane = tid & 31;
    const int g    = lane >> 2;                 // row within m16 group
    const int t    = lane & 3;                  // thread-in-group
    const float scale = 0.088388347648318447f;  // 1/sqrt(128)
    const unsigned FULL = 0xFFFFFFFFu;

    // GEMM1 K ldmatrix per-lane address (b16 x4 over 32-bit tf32 rows)
    const int mrow   = lane & 7;
    const int mq     = lane >> 3;
    const int nb_off = mq >> 1;
    const int half_  = mq & 1;
    const uint32_t kA0 = sbase + ((uint32_t)((nb_off * 8 + mrow) * KSTR + half_ * 4) << 2);

    // GEMM2 V^T ldmatrix per-lane address (fp16, n16k16 per ldsm4):
    //   matrix j = lane/8: j0=(nbA,kc0) j1=(nbA,kc1) j2=(nbA+1,kc0) j3=(nbA+1,kc1)
    const int dly = (lane & 7) + ((lane >> 4) & 1) * 8;   // d-row within 16-block
    const int kc  = (lane >> 3) & 1;                      // k8 chunk
    const uint32_t vB0 = sbase + VOFFB + (uint32_t)(dly * VSTRB + kc * 16);

    for (;;) {
        // ---- pop next work unit ----
        if (tid == 0) smem[WSLOT] = (uint32_t)atomicAdd(&g_next, 1);
        __syncthreads();
        const int u = (int)smem[WSLOT];
        if (u >= nunits) break;

        const int b     = g_order[u / nq];
        const int qb    = (u % nq) * BQ + w * 16;    // this warp's 16 q-rows
        const int valid = vlen[b];

        const float*  kcb = g_Kc + (size_t)b * Kn * DD;
        const __half* vtb = g_Vt + (size_t)b * DD * Kn;

        // ---- Q fragments in registers (scale + tf32 folded) ----
        uint32_t qf[16][4];
        {
            const float* qp = Qg + ((size_t)b * Qn + qb) * DD;
            #pragma unroll
            for (int s = 0; s < 16; s++) {
                const int c = s * 8 + t;
                qf[s][0] = f2tf(qp[(size_t)g * DD + c] * scale);
                qf[s][1] = f2tf(qp[(size_t)(g + 8) * DD + c] * scale);
                qf[s][2] = f2tf(qp[(size_t)g * DD + c + 4] * scale);
                qf[s][3] = f2tf(qp[(size_t)(g + 8) * DD + c + 4] * scale);
            }
        }

        float oacc[16][4];
        #pragma unroll
        for (int i = 0; i < 16; i++)
            { oacc[i][0] = oacc[i][1] = oacc[i][2] = oacc[i][3] = 0.f; }
        float lac0 = 0.f, lac1 = 0.f;

        const int ktiles = (valid + BK - 1) / BK;

        auto load_tile = [&](int kt, int bf) {
            const uint32_t bb = sbase + (uint32_t)bf * BUFB;
            const int k0 = kt * BK;
            #pragma unroll
            for (int c = 0; c < 8; c++) {            // K: 2048 float4 chunks
                const int idx = tid + NTH * c;
                const int r = idx >> 5, c4 = idx & 31;
                cpa16(bb + ((uint32_t)(r * KSTR + c4 * 4) << 2),
                      kcb + ((size_t)(k0 + r) * DD + c4 * 4));
            }
            #pragma unroll
            for (int c = 0; c < 4; c++) {            // V^T: 1024 16B chunks
                const int idx = tid + NTH * c;
                const int d = idx >> 3, k8 = idx & 7;
                cpa16(bb + VOFFB + (uint32_t)(d * VSTRB + k8 * 16),
                      vtb + ((size_t)d * Kn + k0 + k8 * 8));
            }
        };

        load_tile(0, 0);
        CPA_COMMIT();

        int buf = 0;
        for (int kt = 0; kt < ktiles; kt++) {
            const int k0 = kt * BK;

            if (kt + 1 < ktiles) {
                load_tile(kt + 1, buf ^ 1);
                CPA_COMMIT();
                CPA_WAIT(1);
            } else {
                CPA_WAIT(0);
            }
            __syncthreads();

            const uint32_t boff = (uint32_t)buf * BUFB;

            // ---- GEMM1: S(16x64) = Q . K^T (tf32) ----
            float sacc[8][4];
            #pragma unroll
            for (int i = 0; i < 8; i++)
                { sacc[i][0] = sacc[i][1] = sacc[i][2] = sacc[i][3] = 0.f; }

            #pragma unroll
            for (int s = 0; s < 16; s++) {
                #pragma unroll
                for (int nbp = 0; nbp < 4; nbp++) {
                    uint32_t kb[4];
                    ldsm4(kb, kA0 + boff + nbp * (16 * KSTR * 4) + s * 32);
                    mma8(sacc[2 * nbp],     qf[s], kb[0], kb[1]);
                    mma8(sacc[2 * nbp + 1], qf[s], kb[2], kb[3]);
                }
            }

            // ---- mask + exp + row-sums; pack P to fp16 (== A-frag layout) ----
            uint32_t ph[8][2];
            #pragma unroll
            for (int nb = 0; nb < 8; nb++) {
                const int c0 = k0 + nb * 8 + 2 * t;
                const bool m0 = c0 < valid, m1 = (c0 + 1) < valid;
                float p0 = m0 ? __expf(sacc[nb][0]) : 0.f;
                float p1 = m1 ? __expf(sacc[nb][1]) : 0.f;
                float p2 = m0 ? __expf(sacc[nb][2]) : 0.f;
                float p3 = m1 ? __expf(sacc[nb][3]) : 0.f;
                lac0 += p0 + p1;  lac1 += p2 + p3;
                __half2 h0 = __floats2half2_rn(p0, p1);   // (row g,   k 2t,2t+1)
                __half2 h1 = __floats2half2_rn(p2, p3);   // (row g+8, k 2t,2t+1)
                ph[nb][0] = *(uint32_t*)&h0;
                ph[nb][1] = *(uint32_t*)&h1;
            }

            // ---- GEMM2: O(16x128) += P . V (fp16 m16n8k16, no shuffles) ----
            #pragma unroll
            for (int i = 0; i < 4; i++) {            // k16 chunk over 64 keys
                uint32_t a[4];
                a[0] = ph[2 * i][0];     // (g,   k 0..1 of chunk)
                a[1] = ph[2 * i][1];     // (g+8, k 0..1)
                a[2] = ph[2 * i + 1][0]; // (g,   k 8..9)
                a[3] = ph[2 * i + 1][1]; // (g+8, k 8..9)
                #pragma unroll
                for (int nbp = 0; nbp < 8; nbp++) {  // n16 block over d
                    uint32_t vb[4];
                    ldsm4(vb, vB0 + boff + (uint32_t)(nbp * 16 * VSTRB + i * 32));
                    mma16h(oacc[2 * nbp],     a, vb[0], vb[1]);
                    mma16h(oacc[2 * nbp + 1], a, vb[2], vb[3]);
                }
            }

            __syncthreads();    // buffer reusable before next-next cp.async
            buf ^= 1;
        }

        // ---- epilogue: reduce row sums in quad, normalize, store ----
        float l0 = lac0, l1 = lac1;
        l0 += __shfl_xor_sync(FULL, l0, 1);
        l0 += __shfl_xor_sync(FULL, l0, 2);
        l1 += __shfl_xor_sync(FULL, l1, 1);
        l1 += __shfl_xor_sync(FULL, l1, 2);
        const float inv0 = 1.0f / l0;
        const float inv1 = 1.0f / l1;

        float2* o0 = (float2*)(Og + ((size_t)b * Qn + qb + g) * DD);
        float2* o1 = (float2*)(Og + ((size_t)b * Qn + qb + g + 8) * DD);
        #pragma unroll
        for (int nb = 0; nb < 16; nb++) {
            o0[nb * 4 + t] = make_float2(oacc[nb][0] * inv0, oacc[nb][1] * inv0);
            o1[nb * 4 + t] = make_float2(oacc[nb][2] * inv1, oacc[nb][3] * inv1);
        }
    }
}

extern "C" void kernel_launch(void* const* d_in, const int* in_sizes, int n_in,
                              void* d_out, int out_size)
{
    const float* Q  = (const float*)d_in[0];
    const float* K  = (const float*)d_in[1];
    const float* V  = (const float*)d_in[2];
    const int*   vl = (const int*)d_in[3];

    const int B  = in_sizes[3];
    const int Qn = in_sizes[0] / (B * DD);
    const int Kn = in_sizes[1] / (B * DD);
    const int nq = Qn / BQ;
    const int nunits = B * nq;

    const size_t n4 = (size_t)B * Kn * DD / 4;
    kconv<<<(unsigned)((n4 + 255) / 256), 256>>>(K, n4);

    dim3 tg(Kn / 32, DD / 32, B);
    vtrans<<<tg, dim3(32, 8)>>>(V, Kn);

    sched<<<1, 32>>>(vl, B);

    int dev = 0, nsm = 148;
    cudaGetDevice(&dev);
    cudaDeviceGetAttribute(&nsm, cudaDevAttrMultiProcessorCount, dev);
    if (nsm > nunits) nsm = nunits;

    cudaFuncSetAttribute(attn_mma, cudaFuncAttributeMaxDynamicSharedMemorySize,
                         SMEMB);
    attn_mma<<<nsm, NTH, SMEMB>>>(Q, vl, (float*)d_out, Qn, Kn, nq, nunits);
}

// round 9
// speedup vs baseline: 7.4431x; 1.2793x over previous
#include <cuda_runtime.h>
#include <cuda_fp16.h>
#include <cstdint>

// Fused masked SDPA, both GEMMs via mma.sync fp16 (baseline PTX, compute_103).
// fp16 mantissa == tf32 mantissa (10+1 bits) -> same accuracy, half traffic.
// GEMM1: Q(fp16 regs) x K(fp16 smem, non-trans ldsm).  Accum f32.
// GEMM2: P(fp16 regs, == S D-frag layout, no shuffles) x V^T(fp16 smem).
// Pre-pass 1: K -> g_Kc (fp16). Pre-pass 2: V -> g_Vt (fp16, transposed).
// sched: LPT batch order. Main: persistent CTAs, cp.async double-buffered.

#define DD    128
#define BQ    128
#define BK    64
#define NTH   256
#define KSTRB 272                       // K smem row stride (bytes, 136 halfs)
#define VSTRB 144                       // V^T smem row stride (bytes, 72 halfs)
#define VOFFB (BK * KSTRB)              // 17408: V^T offset within buffer
#define BUFB  (VOFFB + DD * VSTRB)      // 35840 B per buffer
#define SMEMB (2 * BUFB + 16)
#define WSLOT (2 * BUFB / 4)

__device__ __half g_Vt[16ull * 128ull * 4096ull];  // [B][d][key] fp16
__device__ __half g_Kc[16ull * 4096ull * 128ull];  // [B][key][d] fp16
__device__ int    g_next;
__device__ int    g_order[64];

__device__ __forceinline__ uint32_t smem_u32(const void* p) {
    uint32_t a;
    asm("{ .reg .u64 t; cvta.to.shared.u64 t, %1; cvt.u32.u64 %0, t; }"
        : "=r"(a) : "l"(p));
    return a;
}

__device__ __forceinline__ void ldsm4(uint32_t* r, uint32_t addr) {
    asm volatile("ldmatrix.sync.aligned.m8n8.x4.shared.b16 {%0,%1,%2,%3}, [%4];"
                 : "=r"(r[0]), "=r"(r[1]), "=r"(r[2]), "=r"(r[3]) : "r"(addr));
}

__device__ __forceinline__ void mma16h(float* d, const uint32_t* a,
                                       uint32_t b0, uint32_t b1) {
    asm volatile(
        "mma.sync.aligned.m16n8k16.row.col.f32.f16.f16.f32 "
        "{%0,%1,%2,%3}, {%4,%5,%6,%7}, {%8,%9}, {%0,%1,%2,%3};"
        : "+f"(d[0]), "+f"(d[1]), "+f"(d[2]), "+f"(d[3])
        : "r"(a[0]), "r"(a[1]), "r"(a[2]), "r"(a[3]), "r"(b0), "r"(b1));
}

__device__ __forceinline__ void cpa16(uint32_t dst, const void* src) {
    asm volatile("cp.async.cg.shared.global [%0], [%1], 16;"
                 :: "r"(dst), "l"(src) : "memory");
}
#define CPA_COMMIT() asm volatile("cp.async.commit_group;" ::: "memory")
#define CPA_WAIT(n)  asm volatile("cp.async.wait_group %0;" :: "n"(n) : "memory")

// ---------------- pre-pass 1: K -> fp16 copy ----------------
__global__ void kconv(const float* __restrict__ Kg, size_t n4) {
    size_t i = (size_t)blockIdx.x * blockDim.x + threadIdx.x;
    if (i < n4) {
        float4 v = ((const float4*)Kg)[i];
        __half2 h0 = __floats2half2_rn(v.x, v.y);
        __half2 h1 = __floats2half2_rn(v.z, v.w);
        ((uint2*)g_Kc)[i] = make_uint2(*(uint32_t*)&h0, *(uint32_t*)&h1);
    }
}

// ---------------- pre-pass 2: V -> g_Vt[b][d][key] (fp16) ----------------
__global__ void vtrans(const float* __restrict__ Vg, int Kn) {
    __shared__ float tile[32][33];
    const int b  = blockIdx.z;
    const int k0 = blockIdx.x * 32;
    const int d0 = blockIdx.y * 32;
    const int tx = threadIdx.x, ty = threadIdx.y;

    const float* src = Vg + ((size_t)b * Kn + k0) * DD + d0;
    #pragma unroll
    for (int j = 0; j < 4; j++)
        tile[ty + 8 * j][tx] = src[(size_t)(ty + 8 * j) * DD + tx];
    __syncthreads();

    __half* dst = g_Vt + ((size_t)b * DD + d0) * Kn + k0;
    #pragma unroll
    for (int j = 0; j < 4; j++)
        dst[(size_t)(ty + 8 * j) * Kn + tx] = __float2half_rn(tile[tx][ty + 8 * j]);
}

// ---------------- scheduler: LPT batch order + counter reset ----------------
__global__ void sched(const int* __restrict__ vlen, int B) {
    if (threadIdx.x == 0) {
        int idx[64], vl[64];
        for (int i = 0; i < B; i++) { idx[i] = i; vl[i] = vlen[i]; }
        for (int i = 1; i < B; i++) {           // insertion sort desc, stable
            int vi = vl[i], ii = idx[i], j = i - 1;
            while (j >= 0 && vl[j] < vi) {
                vl[j + 1] = vl[j]; idx[j + 1] = idx[j]; j--;
            }
            vl[j + 1] = vi; idx[j + 1] = ii;
        }
        for (int i = 0; i < B; i++) g_order[i] = idx[i];
        g_next = 0;
    }
}

// ---------------- main fused attention (persistent) ----------------
__global__ __launch_bounds__(NTH, 1)
void attn_mma(const float* __restrict__ Qg, const int* __restrict__ vlen,
              float* __restrict__ Og, int Qn, int Kn, int nq, int nunits)
{
    extern __shared__ uint32_t smem[];  // 2 x (K [64][136]h ++ V^T [128][72]h)
    const uint32_t sbase = smem_u32(smem);

    const int tid  = threadIdx.x;
    const int w    = tid >> 5;
    const int lane = tid & 31;
    const int g    = lane >> 2;                 // row within m16 group
    const int t    = lane & 3;                  // thread-in-group
    const float scale = 0.088388347648318447f;  // 1/sqrt(128)
    const unsigned FULL = 0xFFFFFFFFu;

    // ldmatrix per-lane address pattern (shared by K and V^T tiles):
    //   matrices: m0=(rows 0-7, chunk0) m1=(rows 0-7, chunk1)
    //             m2=(rows 8-15, chunk0) m3=(rows 8-15, chunk1)
    const int rly = (lane & 7) + ((lane >> 4) & 1) * 8;   // row within 16-block
    const int cc  = (lane >> 3) & 1;                      // 16B chunk (8 halfs)
    const uint32_t kB0 = sbase + (uint32_t)(rly * KSTRB + cc * 16);
    const uint32_t vB0 = sbase + VOFFB + (uint32_t)(rly * VSTRB + cc * 16);

    for (;;) {
        // ---- pop next work unit ----
        if (tid == 0) smem[WSLOT] = (uint32_t)atomicAdd(&g_next, 1);
        __syncthreads();
        const int u = (int)smem[WSLOT];
        if (u >= nunits) break;

        const int b     = g_order[u / nq];
        const int qb    = (u % nq) * BQ + w * 16;    // this warp's 16 q-rows
        const int valid = vlen[b];

        const __half* kcb = g_Kc + (size_t)b * Kn * DD;
        const __half* vtb = g_Vt + (size_t)b * DD * Kn;

        // ---- Q fragments in registers (scale folded, fp16 packed) ----
        // qf[c] = A-frag of k16 chunk c: a0=(g,2t..), a1=(g+8,2t..),
        //         a2=(g,8+2t..), a3=(g+8,8+2t..)
        uint32_t qf[8][4];
        {
            const float* q0 = Qg + ((size_t)b * Qn + qb + g) * DD;
            const float* q1 = Qg + ((size_t)b * Qn + qb + g + 8) * DD;
            #pragma unroll
            for (int c = 0; c < 8; c++) {
                const int d0 = c * 16 + 2 * t;
                float2 x0 = *(const float2*)(q0 + d0);
                float2 x1 = *(const float2*)(q1 + d0);
                float2 y0 = *(const float2*)(q0 + d0 + 8);
                float2 y1 = *(const float2*)(q1 + d0 + 8);
                __half2 h;
                h = __floats2half2_rn(x0.x * scale, x0.y * scale); qf[c][0] = *(uint32_t*)&h;
                h = __floats2half2_rn(x1.x * scale, x1.y * scale); qf[c][1] = *(uint32_t*)&h;
                h = __floats2half2_rn(y0.x * scale, y0.y * scale); qf[c][2] = *(uint32_t*)&h;
                h = __floats2half2_rn(y1.x * scale, y1.y * scale); qf[c][3] = *(uint32_t*)&h;
            }
        }

        float oacc[16][4];
        #pragma unroll
        for (int i = 0; i < 16; i++)
            { oacc[i][0] = oacc[i][1] = oacc[i][2] = oacc[i][3] = 0.f; }
        float lac0 = 0.f, lac1 = 0.f;

        const int ktiles = (valid + BK - 1) / BK;

        auto load_tile = [&](int kt, int bf) {
            const uint32_t bb = sbase + (uint32_t)bf * BUFB;
            const int k0 = kt * BK;
            #pragma unroll
            for (int c = 0; c < 4; c++) {            // K: 1024 16B chunks
                const int idx = tid + NTH * c;
                const int r = idx >> 4, c16 = idx & 15;
                cpa16(bb + (uint32_t)(r * KSTRB + c16 * 16),
                      kcb + ((size_t)(k0 + r) * DD + c16 * 8));
            }
            #pragma unroll
            for (int c = 0; c < 4; c++) {            // V^T: 1024 16B chunks
                const int idx = tid + NTH * c;
                const int d = idx >> 3, k8 = idx & 7;
                cpa16(bb + VOFFB + (uint32_t)(d * VSTRB + k8 * 16),
                      vtb + ((size_t)d * Kn + k0 + k8 * 8));
            }
        };

        load_tile(0, 0);
        CPA_COMMIT();

        int buf = 0;
        for (int kt = 0; kt < ktiles; kt++) {
            const int k0 = kt * BK;

            if (kt + 1 < ktiles) {
                load_tile(kt + 1, buf ^ 1);
                CPA_COMMIT();
                CPA_WAIT(1);
            } else {
                CPA_WAIT(0);
            }
            __syncthreads();

            const uint32_t boff = (uint32_t)buf * BUFB;

            // ---- GEMM1: S(16x64) = Q . K^T (fp16 m16n8k16) ----
            // B-frag pairs along k == d-contiguous in K[key][d] -> non-trans.
            float sacc[8][4];
            #pragma unroll
            for (int i = 0; i < 8; i++)
                { sacc[i][0] = sacc[i][1] = sacc[i][2] = sacc[i][3] = 0.f; }

            #pragma unroll
            for (int c = 0; c < 8; c++) {            // k16 chunk over d
                #pragma unroll
                for (int ng = 0; ng < 4; ng++) {     // n16 group over keys
                    uint32_t kb[4];
                    ldsm4(kb, kB0 + boff + (uint32_t)(ng * 16 * KSTRB + c * 32));
                    mma16h(sacc[2 * ng],     qf[c], kb[0], kb[1]);
                    mma16h(sacc[2 * ng + 1], qf[c], kb[2], kb[3]);
                }
            }

            // ---- mask + exp + row-sums; pack P to fp16 (== A-frag layout) ----
            uint32_t ph[8][2];
            #pragma unroll
            for (int nb = 0; nb < 8; nb++) {
                const int c0 = k0 + nb * 8 + 2 * t;
                const bool m0 = c0 < valid, m1 = (c0 + 1) < valid;
                float p0 = m0 ? __expf(sacc[nb][0]) : 0.f;
                float p1 = m1 ? __expf(sacc[nb][1]) : 0.f;
                float p2 = m0 ? __expf(sacc[nb][2]) : 0.f;
                float p3 = m1 ? __expf(sacc[nb][3]) : 0.f;
                lac0 += p0 + p1;  lac1 += p2 + p3;
                __half2 h0 = __floats2half2_rn(p0, p1);   // (row g,   k 2t,2t+1)
                __half2 h1 = __floats2half2_rn(p2, p3);   // (row g+8, k 2t,2t+1)
                ph[nb][0] = *(uint32_t*)&h0;
                ph[nb][1] = *(uint32_t*)&h1;
            }

            // ---- GEMM2: O(16x128) += P . V (fp16 m16n8k16, no shuffles) ----
            #pragma unroll
            for (int i = 0; i < 4; i++) {            // k16 chunk over 64 keys
                uint32_t a[4];
                a[0] = ph[2 * i][0];     // (g,   k 0..1 of chunk)
                a[1] = ph[2 * i][1];     // (g+8, k 0..1)
                a[2] = ph[2 * i + 1][0]; // (g,   k 8..9)
                a[3] = ph[2 * i + 1][1]; // (g+8, k 8..9)
                #pragma unroll
                for (int nbp = 0; nbp < 8; nbp++) {  // n16 block over d
                    uint32_t vb[4];
                    ldsm4(vb, vB0 + boff + (uint32_t)(nbp * 16 * VSTRB + i * 32));
                    mma16h(oacc[2 * nbp],     a, vb[0], vb[1]);
                    mma16h(oacc[2 * nbp + 1], a, vb[2], vb[3]);
                }
            }

            __syncthreads();    // buffer reusable before next-next cp.async
            buf ^= 1;
        }

        // ---- epilogue: reduce row sums in quad, normalize, store ----
        float l0 = lac0, l1 = lac1;
        l0 += __shfl_xor_sync(FULL, l0, 1);
        l0 += __shfl_xor_sync(FULL, l0, 2);
        l1 += __shfl_xor_sync(FULL, l1, 1);
        l1 += __shfl_xor_sync(FULL, l1, 2);
        const float inv0 = 1.0f / l0;
        const float inv1 = 1.0f / l1;

        float2* o0 = (float2*)(Og + ((size_t)b * Qn + qb + g) * DD);
        float2* o1 = (float2*)(Og + ((size_t)b * Qn + qb + g + 8) * DD);
        #pragma unroll
        for (int nb = 0; nb < 16; nb++) {
            o0[nb * 4 + t] = make_float2(oacc[nb][0] * inv0, oacc[nb][1] * inv0);
            o1[nb * 4 + t] = make_float2(oacc[nb][2] * inv1, oacc[nb][3] * inv1);
        }
    }
}

extern "C" void kernel_launch(void* const* d_in, const int* in_sizes, int n_in,
                              void* d_out, int out_size)
{
    const float* Q  = (const float*)d_in[0];
    const float* K  = (const float*)d_in[1];
    const float* V  = (const float*)d_in[2];
    const int*   vl = (const int*)d_in[3];

    const int B  = in_sizes[3];
    const int Qn = in_sizes[0] / (B * DD);
    const int Kn = in_sizes[1] / (B * DD);
    const int nq = Qn / BQ;
    const int nunits = B * nq;

    const size_t n4 = (size_t)B * Kn * DD / 4;
    kconv<<<(unsigned)((n4 + 255) / 256), 256>>>(K, n4);

    dim3 tg(Kn / 32, DD / 32, B);
    vtrans<<<tg, dim3(32, 8)>>>(V, Kn);

    sched<<<1, 32>>>(vl, B);

    int dev = 0, nsm = 148;
    cudaGetDevice(&dev);
    cudaDeviceGetAttribute(&nsm, cudaDevAttrMultiProcessorCount, dev);
    if (nsm > nunits) nsm = nunits;

    cudaFuncSetAttribute(attn_mma, cudaFuncAttributeMaxDynamicSharedMemorySize,
                         SMEMB);
    attn_mma<<<nsm, NTH, SMEMB>>>(Q, vl, (float*)d_out, Qn, Kn, nq, nunits);
}

// round 10
// speedup vs baseline: 7.4972x; 1.0073x over previous
#include <cuda_runtime.h>
#include <cuda_fp16.h>
#include <cstdint>

// Fused masked SDPA, both GEMMs via mma.sync fp16 (baseline PTX, compute_103).
// 128-thread CTAs (4 warps, BQ=64), 2 CTAs/SM for latency coverage.
// GEMM1: Q(fp16 regs) x K(fp16 smem, non-trans ldsm). Accum f32.
// GEMM2: P(fp16 regs, == S D-frag layout, no shuffles) x V^T(fp16 smem).
// Pre-pass 1: K -> g_Kc (fp16). Pre-pass 2: V -> g_Vt (fp16, transposed).
// sched: LPT batch order. Persistent CTAs, cp.async double-buffered.

#define DD    128
#define BQ    64
#define BK    64
#define NTH   128
#define KSTRB 272                       // K smem row stride (bytes, 136 halfs)
#define VSTRB 144                       // V^T smem row stride (bytes, 72 halfs)
#define VOFFB (BK * KSTRB)              // 17408: V^T offset within buffer
#define BUFB  (VOFFB + DD * VSTRB)      // 35840 B per buffer
#define SMEMB (2 * BUFB + 16)
#define WSLOT (2 * BUFB / 4)

__device__ __half g_Vt[16ull * 128ull * 4096ull];  // [B][d][key] fp16
__device__ __half g_Kc[16ull * 4096ull * 128ull];  // [B][key][d] fp16
__device__ int    g_next;
__device__ int    g_order[64];

__device__ __forceinline__ uint32_t smem_u32(const void* p) {
    uint32_t a;
    asm("{ .reg .u64 t; cvta.to.shared.u64 t, %1; cvt.u32.u64 %0, t; }"
        : "=r"(a) : "l"(p));
    return a;
}

__device__ __forceinline__ void ldsm4(uint32_t* r, uint32_t addr) {
    asm volatile("ldmatrix.sync.aligned.m8n8.x4.shared.b16 {%0,%1,%2,%3}, [%4];"
                 : "=r"(r[0]), "=r"(r[1]), "=r"(r[2]), "=r"(r[3]) : "r"(addr));
}

__device__ __forceinline__ void mma16h(float* d, const uint32_t* a,
                                       uint32_t b0, uint32_t b1) {
    asm volatile(
        "mma.sync.aligned.m16n8k16.row.col.f32.f16.f16.f32 "
        "{%0,%1,%2,%3}, {%4,%5,%6,%7}, {%8,%9}, {%0,%1,%2,%3};"
        : "+f"(d[0]), "+f"(d[1]), "+f"(d[2]), "+f"(d[3])
        : "r"(a[0]), "r"(a[1]), "r"(a[2]), "r"(a[3]), "r"(b0), "r"(b1));
}

__device__ __forceinline__ void cpa16(uint32_t dst, const void* src) {
    asm volatile("cp.async.cg.shared.global [%0], [%1], 16;"
                 :: "r"(dst), "l"(src) : "memory");
}
#define CPA_COMMIT() asm volatile("cp.async.commit_group;" ::: "memory")
#define CPA_WAIT(n)  asm volatile("cp.async.wait_group %0;" :: "n"(n) : "memory")

// ---------------- pre-pass 1: K -> fp16 copy ----------------
__global__ void kconv(const float* __restrict__ Kg, size_t n4) {
    size_t i = (size_t)blockIdx.x * blockDim.x + threadIdx.x;
    if (i < n4) {
        float4 v = ((const float4*)Kg)[i];
        __half2 h0 = __floats2half2_rn(v.x, v.y);
        __half2 h1 = __floats2half2_rn(v.z, v.w);
        ((uint2*)g_Kc)[i] = make_uint2(*(uint32_t*)&h0, *(uint32_t*)&h1);
    }
}

// ---------------- pre-pass 2: V -> g_Vt[b][d][key] (fp16) ----------------
__global__ void vtrans(const float* __restrict__ Vg, int Kn) {
    __shared__ float tile[32][33];
    const int b  = blockIdx.z;
    const int k0 = blockIdx.x * 32;
    const int d0 = blockIdx.y * 32;
    const int tx = threadIdx.x, ty = threadIdx.y;

    const float* src = Vg + ((size_t)b * Kn + k0) * DD + d0;
    #pragma unroll
    for (int j = 0; j < 4; j++)
        tile[ty + 8 * j][tx] = src[(size_t)(ty + 8 * j) * DD + tx];
    __syncthreads();

    __half* dst = g_Vt + ((size_t)b * DD + d0) * Kn + k0;
    #pragma unroll
    for (int j = 0; j < 4; j++)
        dst[(size_t)(ty + 8 * j) * Kn + tx] = __float2half_rn(tile[tx][ty + 8 * j]);
}

// ---------------- scheduler: LPT batch order + counter reset ----------------
__global__ void sched(const int* __restrict__ vlen, int B) {
    if (threadIdx.x == 0) {
        int idx[64], vl[64];
        for (int i = 0; i < B; i++) { idx[i] = i; vl[i] = vlen[i]; }
        for (int i = 1; i < B; i++) {           // insertion sort desc, stable
            int vi = vl[i], ii = idx[i], j = i - 1;
            while (j >= 0 && vl[j] < vi) {
                vl[j + 1] = vl[j]; idx[j + 1] = idx[j]; j--;
            }
            vl[j + 1] = vi; idx[j + 1] = ii;
        }
        for (int i = 0; i < B; i++) g_order[i] = idx[i];
        g_next = 0;
    }
}

// ---------------- main fused attention (persistent, 2 CTAs/SM) ----------------
__global__ __launch_bounds__(NTH, 2)
void attn_mma(const float* __restrict__ Qg, const int* __restrict__ vlen,
              float* __restrict__ Og, int Qn, int Kn, int nq, int nunits)
{
    extern __shared__ uint32_t smem[];  // 2 x (K [64][136]h ++ V^T [128][72]h)
    const uint32_t sbase = smem_u32(smem);

    const int tid  = threadIdx.x;
    const int w    = tid >> 5;                  // 0..3
    const int lane = tid & 31;
    const int g    = lane >> 2;                 // row within m16 group
    const int t    = lane & 3;                  // thread-in-group
    const float scale = 0.088388347648318447f;  // 1/sqrt(128)
    const unsigned FULL = 0xFFFFFFFFu;

    // ldmatrix per-lane address pattern (shared by K and V^T tiles):
    //   matrices: m0=(rows 0-7, chunk0) m1=(rows 0-7, chunk1)
    //             m2=(rows 8-15, chunk0) m3=(rows 8-15, chunk1)
    const int rly = (lane & 7) + ((lane >> 4) & 1) * 8;   // row within 16-block
    const int cc  = (lane >> 3) & 1;                      // 16B chunk (8 halfs)
    const uint32_t kB0 = sbase + (uint32_t)(rly * KSTRB + cc * 16);
    const uint32_t vB0 = sbase + VOFFB + (uint32_t)(rly * VSTRB + cc * 16);

    for (;;) {
        // ---- pop next work unit ----
        if (tid == 0) smem[WSLOT] = (uint32_t)atomicAdd(&g_next, 1);
        __syncthreads();
        const int u = (int)smem[WSLOT];
        if (u >= nunits) break;

        const int b     = g_order[u / nq];
        const int qb    = (u % nq) * BQ + w * 16;    // this warp's 16 q-rows
        const int valid = vlen[b];

        const __half* kcb = g_Kc + (size_t)b * Kn * DD;
        const __half* vtb = g_Vt + (size_t)b * DD * Kn;

        // ---- Q fragments in registers (scale folded, fp16 packed) ----
        uint32_t qf[8][4];
        {
            const float* q0 = Qg + ((size_t)b * Qn + qb + g) * DD;
            const float* q1 = Qg + ((size_t)b * Qn + qb + g + 8) * DD;
            #pragma unroll
            for (int c = 0; c < 8; c++) {
                const int d0 = c * 16 + 2 * t;
                float2 x0 = *(const float2*)(q0 + d0);
                float2 x1 = *(const float2*)(q1 + d0);
                float2 y0 = *(const float2*)(q0 + d0 + 8);
                float2 y1 = *(const float2*)(q1 + d0 + 8);
                __half2 h;
                h = __floats2half2_rn(x0.x * scale, x0.y * scale); qf[c][0] = *(uint32_t*)&h;
                h = __floats2half2_rn(x1.x * scale, x1.y * scale); qf[c][1] = *(uint32_t*)&h;
                h = __floats2half2_rn(y0.x * scale, y0.y * scale); qf[c][2] = *(uint32_t*)&h;
                h = __floats2half2_rn(y1.x * scale, y1.y * scale); qf[c][3] = *(uint32_t*)&h;
            }
        }

        float oacc[16][4];
        #pragma unroll
        for (int i = 0; i < 16; i++)
            { oacc[i][0] = oacc[i][1] = oacc[i][2] = oacc[i][3] = 0.f; }
        float lac0 = 0.f, lac1 = 0.f;

        const int ktiles = (valid + BK - 1) / BK;

        auto load_tile = [&](int kt, int bf) {
            const uint32_t bb = sbase + (uint32_t)bf * BUFB;
            const int k0 = kt * BK;
            #pragma unroll
            for (int c = 0; c < 8; c++) {            // K: 1024 16B chunks
                const int idx = tid + NTH * c;
                const int r = idx >> 4, c16 = idx & 15;
                cpa16(bb + (uint32_t)(r * KSTRB + c16 * 16),
                      kcb + ((size_t)(k0 + r) * DD + c16 * 8));
            }
            #pragma unroll
            for (int c = 0; c < 8; c++) {            // V^T: 1024 16B chunks
                const int idx = tid + NTH * c;
                const int d = idx >> 3, k8 = idx & 7;
                cpa16(bb + VOFFB + (uint32_t)(d * VSTRB + k8 * 16),
                      vtb + ((size_t)d * Kn + k0 + k8 * 8));
            }
        };

        load_tile(0, 0);
        CPA_COMMIT();

        int buf = 0;
        for (int kt = 0; kt < ktiles; kt++) {
            const int k0 = kt * BK;

            if (kt + 1 < ktiles) {
                load_tile(kt + 1, buf ^ 1);
                CPA_COMMIT();
                CPA_WAIT(1);
            } else {
                CPA_WAIT(0);
            }
            __syncthreads();

            const uint32_t boff = (uint32_t)buf * BUFB;

            // ---- GEMM1: S(16x64) = Q . K^T (fp16 m16n8k16) ----
            float sacc[8][4];
            #pragma unroll
            for (int i = 0; i < 8; i++)
                { sacc[i][0] = sacc[i][1] = sacc[i][2] = sacc[i][3] = 0.f; }

            #pragma unroll
            for (int c = 0; c < 8; c++) {            // k16 chunk over d
                #pragma unroll
                for (int ng = 0; ng < 4; ng++) {     // n16 group over keys
                    uint32_t kb[4];
                    ldsm4(kb, kB0 + boff + (uint32_t)(ng * 16 * KSTRB + c * 32));
                    mma16h(sacc[2 * ng],     qf[c], kb[0], kb[1]);
                    mma16h(sacc[2 * ng + 1], qf[c], kb[2], kb[3]);
                }
            }

            // ---- mask + exp + row-sums; pack P to fp16 (== A-frag layout) ----
            uint32_t ph[8][2];
            #pragma unroll
            for (int nb = 0; nb < 8; nb++) {
                const int c0 = k0 + nb * 8 + 2 * t;
                const bool m0 = c0 < valid, m1 = (c0 + 1) < valid;
                float p0 = m0 ? __expf(sacc[nb][0]) : 0.f;
                float p1 = m1 ? __expf(sacc[nb][1]) : 0.f;
                float p2 = m0 ? __expf(sacc[nb][2]) : 0.f;
                float p3 = m1 ? __expf(sacc[nb][3]) : 0.f;
                lac0 += p0 + p1;  lac1 += p2 + p3;
                __half2 h0 = __floats2half2_rn(p0, p1);   // (row g,   k 2t,2t+1)
                __half2 h1 = __floats2half2_rn(p2, p3);   // (row g+8, k 2t,2t+1)
                ph[nb][0] = *(uint32_t*)&h0;
                ph[nb][1] = *(uint32_t*)&h1;
            }

            // ---- GEMM2: O(16x128) += P . V (fp16 m16n8k16, no shuffles) ----
            #pragma unroll
            for (int i = 0; i < 4; i++) {            // k16 chunk over 64 keys
                uint32_t a[4];
                a[0] = ph[2 * i][0];     // (g,   k 0..1 of chunk)
                a[1] = ph[2 * i][1];     // (g+8, k 0..1)
                a[2] = ph[2 * i + 1][0]; // (g,   k 8..9)
                a[3] = ph[2 * i + 1][1]; // (g+8, k 8..9)
                #pragma unroll
                for (int nbp = 0; nbp < 8; nbp++) {  // n16 block over d
                    uint32_t vb[4];
                    ldsm4(vb, vB0 + boff + (uint32_t)(nbp * 16 * VSTRB + i * 32));
                    mma16h(oacc[2 * nbp],     a, vb[0], vb[1]);
                    mma16h(oacc[2 * nbp + 1], a, vb[2], vb[3]);
                }
            }

            __syncthreads();    // buffer reusable before next-next cp.async
            buf ^= 1;
        }

        // ---- epilogue: reduce row sums in quad, normalize, store ----
        float l0 = lac0, l1 = lac1;
        l0 += __shfl_xor_sync(FULL, l0, 1);
        l0 += __shfl_xor_sync(FULL, l0, 2);
        l1 += __shfl_xor_sync(FULL, l1, 1);
        l1 += __shfl_xor_sync(FULL, l1, 2);
        const float inv0 = 1.0f / l0;
        const float inv1 = 1.0f / l1;

        float2* o0 = (float2*)(Og + ((size_t)b * Qn + qb + g) * DD);
        float2* o1 = (float2*)(Og + ((size_t)b * Qn + qb + g + 8) * DD);
        #pragma unroll
        for (int nb = 0; nb < 16; nb++) {
            o0[nb * 4 + t] = make_float2(oacc[nb][0] * inv0, oacc[nb][1] * inv0);
            o1[nb * 4 + t] = make_float2(oacc[nb][2] * inv1, oacc[nb][3] * inv1);
        }
    }
}

extern "C" void kernel_launch(void* const* d_in, const int* in_sizes, int n_in,
                              void* d_out, int out_size)
{
    const float* Q  = (const float*)d_in[0];
    const float* K  = (const float*)d_in[1];
    const float* V  = (const float*)d_in[2];
    const int*   vl = (const int*)d_in[3];

    const int B  = in_sizes[3];
    const int Qn = in_sizes[0] / (B * DD);
    const int Kn = in_sizes[1] / (B * DD);
    const int nq = Qn / BQ;
    const int nunits = B * nq;

    const size_t n4 = (size_t)B * Kn * DD / 4;
    kconv<<<(unsigned)((n4 + 255) / 256), 256>>>(K, n4);

    dim3 tg(Kn / 32, DD / 32, B);
    vtrans<<<tg, dim3(32, 8)>>>(V, Kn);

    sched<<<1, 32>>>(vl, B);

    int dev = 0, nsm = 148;
    cudaGetDevice(&dev);
    cudaDeviceGetAttribute(&nsm, cudaDevAttrMultiProcessorCount, dev);
    int grid = 2 * nsm;
    if (grid > nunits) grid = nunits;

    cudaFuncSetAttribute(attn_mma, cudaFuncAttributeMaxDynamicSharedMemorySize,
                         SMEMB);
    attn_mma<<<grid, NTH, SMEMB>>>(Q, vl, (float*)d_out, Qn, Kn, nq, nunits);
}

// round 11
// speedup vs baseline: 7.7491x; 1.0336x over previous
#include <cuda_runtime.h>
#include <cuda_fp16.h>
#include <cstdint>

// Fused masked SDPA, both GEMMs via mma.sync fp16 (baseline PTX, compute_103).
// 128-thread CTAs (4 warps, BQ=64), 3 CTAs/SM (170-reg cap) for latency cover.
// Tile loop unrolled x2 with literal buffer offsets (const-folded addresses).
// GEMM1: Q(fp16 regs) x K(fp16 smem, non-trans ldsm). Accum f32.
// GEMM2: P(fp16 regs, == S D-frag layout, no shuffles) x V^T(fp16 smem).
// Pre-pass 1: K -> g_Kc (fp16). Pre-pass 2: V -> g_Vt (fp16, transposed).
// sched: LPT batch order. Persistent CTAs, cp.async double-buffered.

#define DD    128
#define BQ    64
#define BK    64
#define NTH   128
#define KSTRB 272                       // K smem row stride (bytes, 136 halfs)
#define VSTRB 144                       // V^T smem row stride (bytes, 72 halfs)
#define VOFFB (BK * KSTRB)              // 17408: V^T offset within buffer
#define BUFB  (VOFFB + DD * VSTRB)      // 35840 B per buffer
#define SMEMB (2 * BUFB + 16)
#define WSLOT (2 * BUFB / 4)

__device__ __half g_Vt[16ull * 128ull * 4096ull];  // [B][d][key] fp16
__device__ __half g_Kc[16ull * 4096ull * 128ull];  // [B][key][d] fp16
__device__ int    g_next;
__device__ int    g_order[64];

__device__ __forceinline__ uint32_t smem_u32(const void* p) {
    uint32_t a;
    asm("{ .reg .u64 t; cvta.to.shared.u64 t, %1; cvt.u32.u64 %0, t; }"
        : "=r"(a) : "l"(p));
    return a;
}

__device__ __forceinline__ void ldsm4(uint32_t* r, uint32_t addr) {
    asm volatile("ldmatrix.sync.aligned.m8n8.x4.shared.b16 {%0,%1,%2,%3}, [%4];"
                 : "=r"(r[0]), "=r"(r[1]), "=r"(r[2]), "=r"(r[3]) : "r"(addr));
}

__device__ __forceinline__ void mma16h(float* d, const uint32_t* a,
                                       uint32_t b0, uint32_t b1) {
    asm volatile(
        "mma.sync.aligned.m16n8k16.row.col.f32.f16.f16.f32 "
        "{%0,%1,%2,%3}, {%4,%5,%6,%7}, {%8,%9}, {%0,%1,%2,%3};"
        : "+f"(d[0]), "+f"(d[1]), "+f"(d[2]), "+f"(d[3])
        : "r"(a[0]), "r"(a[1]), "r"(a[2]), "r"(a[3]), "r"(b0), "r"(b1));
}

__device__ __forceinline__ void cpa16(uint32_t dst, const void* src) {
    asm volatile("cp.async.cg.shared.global [%0], [%1], 16;"
                 :: "r"(dst), "l"(src) : "memory");
}
#define CPA_COMMIT() asm volatile("cp.async.commit_group;" ::: "memory")
#define CPA_WAIT(n)  asm volatile("cp.async.wait_group %0;" :: "n"(n) : "memory")

// ---------------- pre-pass 1: K -> fp16 copy ----------------
__global__ void kconv(const float* __restrict__ Kg, size_t n4) {
    size_t i = (size_t)blockIdx.x * blockDim.x + threadIdx.x;
    if (i < n4) {
        float4 v = ((const float4*)Kg)[i];
        __half2 h0 = __floats2half2_rn(v.x, v.y);
        __half2 h1 = __floats2half2_rn(v.z, v.w);
        ((uint2*)g_Kc)[i] = make_uint2(*(uint32_t*)&h0, *(uint32_t*)&h1);
    }
}

// ---------------- pre-pass 2: V -> g_Vt[b][d][key] (fp16) ----------------
__global__ void vtrans(const float* __restrict__ Vg, int Kn) {
    __shared__ float tile[32][33];
    const int b  = blockIdx.z;
    const int k0 = blockIdx.x * 32;
    const int d0 = blockIdx.y * 32;
    const int tx = threadIdx.x, ty = threadIdx.y;

    const float* src = Vg + ((size_t)b * Kn + k0) * DD + d0;
    #pragma unroll
    for (int j = 0; j < 4; j++)
        tile[ty + 8 * j][tx] = src[(size_t)(ty + 8 * j) * DD + tx];
    __syncthreads();

    __half* dst = g_Vt + ((size_t)b * DD + d0) * Kn + k0;
    #pragma unroll
    for (int j = 0; j < 4; j++)
        dst[(size_t)(ty + 8 * j) * Kn + tx] = __float2half_rn(tile[tx][ty + 8 * j]);
}

// ---------------- scheduler: LPT batch order + counter reset ----------------
__global__ void sched(const int* __restrict__ vlen, int B) {
    if (threadIdx.x == 0) {
        int idx[64], vl[64];
        for (int i = 0; i < B; i++) { idx[i] = i; vl[i] = vlen[i]; }
        for (int i = 1; i < B; i++) {           // insertion sort desc, stable
            int vi = vl[i], ii = idx[i], j = i - 1;
            while (j >= 0 && vl[j] < vi) {
                vl[j + 1] = vl[j]; idx[j + 1] = idx[j]; j--;
            }
            vl[j + 1] = vi; idx[j + 1] = ii;
        }
        for (int i = 0; i < B; i++) g_order[i] = idx[i];
        g_next = 0;
    }
}

// ---------------- main fused attention (persistent, 3 CTAs/SM) ----------------
__global__ __launch_bounds__(NTH, 3)
void attn_mma(const float* __restrict__ Qg, const int* __restrict__ vlen,
              float* __restrict__ Og, int Qn, int Kn, int nq, int nunits)
{
    extern __shared__ uint32_t smem[];  // 2 x (K [64][136]h ++ V^T [128][72]h)
    const uint32_t sbase = smem_u32(smem);

    const int tid  = threadIdx.x;
    const int w    = tid >> 5;                  // 0..3
    const int lane = tid & 31;
    const int g    = lane >> 2;                 // row within m16 group
    const int t    = lane & 3;                  // thread-in-group
    const float scale = 0.088388347648318447f;  // 1/sqrt(128)
    const unsigned FULL = 0xFFFFFFFFu;

    // ldmatrix per-lane address pattern (shared by K and V^T tiles)
    const int rly = (lane & 7) + ((lane >> 4) & 1) * 8;   // row within 16-block
    const int cc  = (lane >> 3) & 1;                      // 16B chunk (8 halfs)
    const uint32_t kB0 = sbase + (uint32_t)(rly * KSTRB + cc * 16);
    const uint32_t vB0 = sbase + VOFFB + (uint32_t)(rly * VSTRB + cc * 16);

    // cp.async per-thread address components (loop-invariant)
    const int ldK_r = tid >> 4, ldK_c = (tid & 15) * 16;       // K rows 0..7(+8)
    const int ldV_d = tid >> 3, ldV_k = (tid & 7) * 16;        // V rows 0..15(+16)

    for (;;) {
        // ---- pop next work unit ----
        if (tid == 0) smem[WSLOT] = (uint32_t)atomicAdd(&g_next, 1);
        __syncthreads();
        const int u = (int)smem[WSLOT];
        if (u >= nunits) break;

        const int b     = g_order[u / nq];
        const int qb    = (u % nq) * BQ + w * 16;    // this warp's 16 q-rows
        const int valid = vlen[b];

        const __half* kcb = g_Kc + (size_t)b * Kn * DD;
        const __half* vtb = g_Vt + (size_t)b * DD * Kn;

        // ---- Q fragments in registers (scale folded, fp16 packed) ----
        uint32_t qf[8][4];
        {
            const float* q0 = Qg + ((size_t)b * Qn + qb + g) * DD;
            const float* q1 = Qg + ((size_t)b * Qn + qb + g + 8) * DD;
            #pragma unroll
            for (int c = 0; c < 8; c++) {
                const int d0 = c * 16 + 2 * t;
                float2 x0 = *(const float2*)(q0 + d0);
                float2 x1 = *(const float2*)(q1 + d0);
                float2 y0 = *(const float2*)(q0 + d0 + 8);
                float2 y1 = *(const float2*)(q1 + d0 + 8);
                __half2 h;
                h = __floats2half2_rn(x0.x * scale, x0.y * scale); qf[c][0] = *(uint32_t*)&h;
                h = __floats2half2_rn(x1.x * scale, x1.y * scale); qf[c][1] = *(uint32_t*)&h;
                h = __floats2half2_rn(y0.x * scale, y0.y * scale); qf[c][2] = *(uint32_t*)&h;
                h = __floats2half2_rn(y1.x * scale, y1.y * scale); qf[c][3] = *(uint32_t*)&h;
            }
        }

        float oacc[16][4];
        #pragma unroll
        for (int i = 0; i < 16; i++)
            { oacc[i][0] = oacc[i][1] = oacc[i][2] = oacc[i][3] = 0.f; }
        float lac0 = 0.f, lac1 = 0.f;

        const int ktiles = (valid + BK - 1) / BK;

        // loader: bb is a literal at every call site -> addresses const-fold
        auto load_tile = [&](int kt, uint32_t bb) {
            const int k0 = kt * BK;
            const __half* ksrc = kcb + (size_t)(k0 + ldK_r) * DD + (ldK_c >> 1);
            uint32_t kdst = sbase + bb + (uint32_t)(ldK_r * KSTRB + ldK_c);
            #pragma unroll
            for (int c = 0; c < 8; c++)            // 8 rows apart per step
                cpa16(kdst + (uint32_t)(c * 8 * KSTRB), ksrc + (size_t)(c * 8) * DD);
            const __half* vsrc = vtb + (size_t)ldV_d * Kn + k0 + (ldV_k >> 1);
            uint32_t vdst = sbase + bb + VOFFB + (uint32_t)(ldV_d * VSTRB + ldV_k);
            #pragma unroll
            for (int c = 0; c < 8; c++)            // 16 d-rows apart per step
                cpa16(vdst + (uint32_t)(c * 16 * VSTRB), vsrc + (size_t)(c * 16) * Kn);
        };

        // one tile step; boff/obff are literals at the two call sites
        auto step = [&](int kt, uint32_t boff, uint32_t obff) {
            const int k0 = kt * BK;
            if (kt + 1 < ktiles) {
                load_tile(kt + 1, obff);
                CPA_COMMIT();
                CPA_WAIT(1);
            } else {
                CPA_WAIT(0);
            }
            __syncthreads();

            // ---- GEMM1: S(16x64) = Q . K^T (fp16 m16n8k16) ----
            float sacc[8][4];
            #pragma unroll
            for (int i = 0; i < 8; i++)
                { sacc[i][0] = sacc[i][1] = sacc[i][2] = sacc[i][3] = 0.f; }

            #pragma unroll
            for (int c = 0; c < 8; c++) {            // k16 chunk over d
                #pragma unroll
                for (int ng = 0; ng < 4; ng++) {     // n16 group over keys
                    uint32_t kb[4];
                    ldsm4(kb, kB0 + boff + (uint32_t)(ng * 16 * KSTRB + c * 32));
                    mma16h(sacc[2 * ng],     qf[c], kb[0], kb[1]);
                    mma16h(sacc[2 * ng + 1], qf[c], kb[2], kb[3]);
                }
            }

            // ---- mask + exp + row-sums; pack P to fp16 (== A-frag layout) ----
            uint32_t ph[8][2];
            #pragma unroll
            for (int nb = 0; nb < 8; nb++) {
                const int c0 = k0 + nb * 8 + 2 * t;
                const bool m0 = c0 < valid, m1 = (c0 + 1) < valid;
                float p0 = m0 ? __expf(sacc[nb][0]) : 0.f;
                float p1 = m1 ? __expf(sacc[nb][1]) : 0.f;
                float p2 = m0 ? __expf(sacc[nb][2]) : 0.f;
                float p3 = m1 ? __expf(sacc[nb][3]) : 0.f;
                lac0 += p0 + p1;  lac1 += p2 + p3;
                __half2 h0 = __floats2half2_rn(p0, p1);
                __half2 h1 = __floats2half2_rn(p2, p3);
                ph[nb][0] = *(uint32_t*)&h0;
                ph[nb][1] = *(uint32_t*)&h1;
            }

            // ---- GEMM2: O(16x128) += P . V (fp16, no shuffles) ----
            #pragma unroll
            for (int i = 0; i < 4; i++) {            // k16 chunk over 64 keys
                uint32_t a[4];
                a[0] = ph[2 * i][0];
                a[1] = ph[2 * i][1];
                a[2] = ph[2 * i + 1][0];
                a[3] = ph[2 * i + 1][1];
                #pragma unroll
                for (int nbp = 0; nbp < 8; nbp++) {  // n16 block over d
                    uint32_t vb[4];
                    ldsm4(vb, vB0 + boff + (uint32_t)(nbp * 16 * VSTRB + i * 32));
                    mma16h(oacc[2 * nbp],     a, vb[0], vb[1]);
                    mma16h(oacc[2 * nbp + 1], a, vb[2], vb[3]);
                }
            }

            __syncthreads();    // buffer reusable before next-next cp.async
        };

        load_tile(0, 0u);
        CPA_COMMIT();

        for (int kt = 0; kt < ktiles; kt += 2) {
            step(kt, 0u, (uint32_t)BUFB);                     // buffer 0
            if (kt + 1 < ktiles)
                step(kt + 1, (uint32_t)BUFB, 0u);             // buffer 1
        }

        // ---- epilogue: reduce row sums in quad, normalize, store ----
        float l0 = lac0, l1 = lac1;
        l0 += __shfl_xor_sync(FULL, l0, 1);
        l0 += __shfl_xor_sync(FULL, l0, 2);
        l1 += __shfl_xor_sync(FULL, l1, 1);
        l1 += __shfl_xor_sync(FULL, l1, 2);
        const float inv0 = 1.0f / l0;
        const float inv1 = 1.0f / l1;

        float2* o0 = (float2*)(Og + ((size_t)b * Qn + qb + g) * DD);
        float2* o1 = (float2*)(Og + ((size_t)b * Qn + qb + g + 8) * DD);
        #pragma unroll
        for (int nb = 0; nb < 16; nb++) {
            o0[nb * 4 + t] = make_float2(oacc[nb][0] * inv0, oacc[nb][1] * inv0);
            o1[nb * 4 + t] = make_float2(oacc[nb][2] * inv1, oacc[nb][3] * inv1);
        }
    }
}

extern "C" void kernel_launch(void* const* d_in, const int* in_sizes, int n_in,
                              void* d_out, int out_size)
{
    const float* Q  = (const float*)d_in[0];
    const float* K  = (const float*)d_in[1];
    const float* V  = (const float*)d_in[2];
    const int*   vl = (const int*)d_in[3];

    const int B  = in_sizes[3];
    const int Qn = in_sizes[0] / (B * DD);
    const int Kn = in_sizes[1] / (B * DD);
    const int nq = Qn / BQ;
    const int nunits = B * nq;

    const size_t n4 = (size_t)B * Kn * DD / 4;
    kconv<<<(unsigned)((n4 + 255) / 256), 256>>>(K, n4);

    dim3 tg(Kn / 32, DD / 32, B);
    vtrans<<<tg, dim3(32, 8)>>>(V, Kn);

    sched<<<1, 32>>>(vl, B);

    int dev = 0, nsm = 148;
    cudaGetDevice(&dev);
    cudaDeviceGetAttribute(&nsm, cudaDevAttrMultiProcessorCount, dev);
    int grid = 3 * nsm;
    if (grid > nunits) grid = nunits;

    cudaFuncSetAttribute(attn_mma, cudaFuncAttributeMaxDynamicSharedMemorySize,
                         SMEMB);
    attn_mma<<<grid, NTH, SMEMB>>>(Q, vl, (float*)d_out, Qn, Kn, nq, nunits);
}